// round 10
// baseline (speedup 1.0000x reference)
#include <cuda_runtime.h>
#include <cuda_bf16.h>

#define Bb 512
#define Hh 1024
#define Nn 16384
#define Mm 128
#define Rr 4
#define Ss 3

#define PADK 40
#define PADW 136
#define PAD64 72
#define PADA 36     // fp32 row stride, 32-wide A tiles (144B)
#define PADB 132    // fp32 row stride, 128-wide B tiles (528B)

// ---------------- scratch ----------------
__device__ __align__(16) float g_k[Bb*Mm];
__device__ __align__(16) float g_e[Bb*Mm];
__device__ __align__(16) float g_a[Bb*Mm];
__device__ float g_beta[Bb], g_gate[Bb], g_slog[Bb*Ss], g_s[Bb*Ss];
__device__ float g_nk[Bb], g_nm[Nn], g_sum[Bb];   // INVERSE norms
__device__ __align__(16) float g_t[(size_t)Bb*Nn];
__device__ __align__(16) __nv_bfloat16 g_mbf[(size_t)Nn*Mm];  // bf16 copy of m (sim only)

// ---------------- helpers ----------------
__device__ __forceinline__ void ldsm4(unsigned* r, const __nv_bfloat16* p) {
    unsigned a = (unsigned)__cvta_generic_to_shared(p);
    asm volatile("ldmatrix.sync.aligned.m8n8.x4.shared.b16 {%0,%1,%2,%3}, [%4];"
        : "=r"(r[0]), "=r"(r[1]), "=r"(r[2]), "=r"(r[3]) : "r"(a));
}
__device__ __forceinline__ void ldsm4t(unsigned* r, const __nv_bfloat16* p) {
    unsigned a = (unsigned)__cvta_generic_to_shared(p);
    asm volatile("ldmatrix.sync.aligned.m8n8.x4.trans.shared.b16 {%0,%1,%2,%3}, [%4];"
        : "=r"(r[0]), "=r"(r[1]), "=r"(r[2]), "=r"(r[3]) : "r"(a));
}
__device__ __forceinline__ void mma16816(float* c, const unsigned* a, const unsigned* b) {
    asm volatile("mma.sync.aligned.m16n8k16.row.col.f32.bf16.bf16.f32 "
        "{%0,%1,%2,%3}, {%4,%5,%6,%7}, {%8,%9}, {%0,%1,%2,%3};"
        : "+f"(c[0]), "+f"(c[1]), "+f"(c[2]), "+f"(c[3])
        : "r"(a[0]), "r"(a[1]), "r"(a[2]), "r"(a[3]), "r"(b[0]), "r"(b[1]));
}
__device__ __forceinline__ void mma1688_tf32(float* c, const float* a, const float* b) {
    asm volatile("mma.sync.aligned.m16n8k8.row.col.f32.tf32.tf32.f32 "
        "{%0,%1,%2,%3}, {%4,%5,%6,%7}, {%8,%9}, {%0,%1,%2,%3};"
        : "+f"(c[0]), "+f"(c[1]), "+f"(c[2]), "+f"(c[3])
        : "r"(__float_as_uint(a[0])), "r"(__float_as_uint(a[1])),
          "r"(__float_as_uint(a[2])), "r"(__float_as_uint(a[3])),
          "r"(__float_as_uint(b[0])), "r"(__float_as_uint(b[1])));
}
__device__ __forceinline__ void cvt_store8(__nv_bfloat16* dst, float4 v0, float4 v1) {
    __nv_bfloat162* d = (__nv_bfloat162*)dst;
    d[0] = __float22bfloat162_rn(make_float2(v0.x, v0.y));
    d[1] = __float22bfloat162_rn(make_float2(v0.z, v0.w));
    d[2] = __float22bfloat162_rn(make_float2(v1.x, v1.y));
    d[3] = __float22bfloat162_rn(make_float2(v1.z, v1.w));
}
// exp2 on the FMA pipe — no MUFU.
__device__ __forceinline__ float fast_exp2(float x) {
    float t = x + 12582912.0f;
    int ri = __float_as_int(t) - 0x4B400000;
    float f = x - (t - 12582912.0f);
    float p = 0.0013333558f;
    p = fmaf(p, f, 0.0096181298f);
    p = fmaf(p, f, 0.0555041087f);
    p = fmaf(p, f, 0.2402265070f);
    p = fmaf(p, f, 0.6931471806f);
    p = fmaf(p, f, 1.0f);
    return __int_as_float(__float_as_int(p) + (ri << 23));
}

// ---------------- kernel 1: controller projections (8x j-parallel) ----------------
__global__ __launch_bounds__(256) void ctrl_kernel(
    const float* __restrict__ h,
    const float* __restrict__ kw, const float* __restrict__ kb,
    const float* __restrict__ bw, const float* __restrict__ bbv,
    const float* __restrict__ gw, const float* __restrict__ gb,
    const float* __restrict__ sw, const float* __restrict__ sb,
    const float* __restrict__ ew, const float* __restrict__ eb,
    const float* __restrict__ aw, const float* __restrict__ ab)
{
    __shared__ float h_s[8][Hh];
    int b0 = blockIdx.x * 8;
    for (int i = threadIdx.x; i < 8*Hh; i += 256)
        h_s[i >> 10][i & 1023] = h[(size_t)(b0 + (i >> 10))*Hh + (i & 1023)];
    __syncthreads();
    int warp = threadIdx.x >> 5, lane = threadIdx.x & 31;
    for (int j = blockIdx.y*8 + warp; j < 3*Mm + 5; j += 64) {
        const float* wrow; float bias; int act;
        if (j < Mm)        { wrow = kw + (size_t)j*Hh;        bias = kb[j];      act = 0; }
        else if (j < 2*Mm) { wrow = ew + (size_t)(j-Mm)*Hh;   bias = eb[j-Mm];   act = 0; }
        else if (j < 3*Mm) { wrow = aw + (size_t)(j-2*Mm)*Hh; bias = ab[j-2*Mm]; act = 0; }
        else if (j == 384) { wrow = bw;                       bias = bbv[0];     act = 2; }
        else if (j == 385) { wrow = gw;                       bias = gb[0];      act = 0; }
        else               { wrow = sw + (size_t)(j-386)*Hh;  bias = sb[j-386];  act = 3; }
        float acc[8];
        #pragma unroll
        for (int q = 0; q < 8; q++) acc[q] = 0.f;
        for (int k = lane; k < Hh; k += 32) {
            float wv = __ldg(wrow + k);
            #pragma unroll
            for (int q = 0; q < 8; q++) acc[q] = fmaf(wv, h_s[q][k], acc[q]);
        }
        #pragma unroll
        for (int q = 0; q < 8; q++) {
            float v = acc[q];
            #pragma unroll
            for (int o = 16; o; o >>= 1) v += __shfl_down_sync(0xffffffffu, v, o);
            if (lane == 0) {
                v += bias;
                if (act == 0) v = fminf(fmaxf(v, 0.f), 1.f);
                else if (act == 2) v = fmaxf(v, 0.f);
                int b = b0 + q;
                if (j < Mm)        g_k[b*Mm + j] = v;
                else if (j < 2*Mm) g_e[b*Mm + (j-Mm)] = v;
                else if (j < 3*Mm) g_a[b*Mm + (j-2*Mm)] = v;
                else if (j == 384) g_beta[b] = v;
                else if (j == 385) g_gate[b] = v;
                else               g_slog[b*Ss + (j-386)] = v;
            }
        }
    }
}

// ---------------- kernel 2a: m inverse norms + bf16 copy + zero r_t ----------------
__global__ __launch_bounds__(256) void prep_m_kernel(const float* __restrict__ m, float* __restrict__ r_out)
{
    int warp = threadIdx.x >> 5, lane = threadIdx.x & 31;
    int bidx = blockIdx.x;
    if (bidx < 2048) {
        int n = bidx*8 + warp;
        float4 v = *(const float4*)(m + (size_t)n*Mm + lane*4);
        __nv_bfloat162* dst = (__nv_bfloat162*)(g_mbf + (size_t)n*Mm + lane*4);
        dst[0] = __float22bfloat162_rn(make_float2(v.x, v.y));
        dst[1] = __float22bfloat162_rn(make_float2(v.z, v.w));
        float ss = v.x*v.x + v.y*v.y + v.z*v.z + v.w*v.w;
        #pragma unroll
        for (int o = 16; o; o >>= 1) ss += __shfl_down_sync(0xffffffffu, ss, o);
        if (lane == 0) g_nm[n] = (ss > 0.f) ? 1.f/sqrtf(ss) : 0.f;
    } else {
        int base = (bidx-2048)*2048 + threadIdx.x*8;
        float4 z = make_float4(0.f,0.f,0.f,0.f);
        *(float4*)(r_out + base)     = z;
        *(float4*)(r_out + base + 4) = z;
    }
}

// ---------------- kernel 2b: k inverse norms + shift softmax ----------------
__global__ __launch_bounds__(256) void prep_k_kernel()
{
    int warp = threadIdx.x >> 5, lane = threadIdx.x & 31;
    int b = blockIdx.x*8 + warp;
    float4 v = *(const float4*)(g_k + (size_t)b*Mm + lane*4);
    float ss = v.x*v.x + v.y*v.y + v.z*v.z + v.w*v.w;
    #pragma unroll
    for (int o = 16; o; o >>= 1) ss += __shfl_down_sync(0xffffffffu, ss, o);
    if (lane == 0) {
        g_nk[b] = (ss > 0.f) ? 1.f/sqrtf(ss) : 0.f;
        g_sum[b] = 0.f;
        float x0 = g_slog[b*Ss+0], x1 = g_slog[b*Ss+1], x2 = g_slog[b*Ss+2];
        float mx = fmaxf(x0, fmaxf(x1, x2));
        float e0 = expf(x0-mx), e1 = expf(x1-mx), e2 = expf(x2-mx);
        float it = 1.f / (e0+e1+e2);
        g_s[b*Ss+0] = e0*it; g_s[b*Ss+1] = e1*it; g_s[b*Ss+2] = e2*it;
    }
}

// ---------------- kernel 3: sim GEMM (bf16 B direct) + poly-exp2 + row sums ----------------
__global__ __launch_bounds__(256) void sim_hmma(int b_off)
{
    __shared__ __align__(16) __nv_bfloat16 As[128*PADK];
    __shared__ __align__(16) __nv_bfloat16 Bs[128*PADK];
    __shared__ float ssum[128];
    int tid = threadIdx.x, lane = tid & 31, w = tid >> 5;
    int n0 = blockIdx.x * 128, b0 = blockIdx.y * 128 + b_off;
    int wm = (w >> 1) * 32, wn = (w & 1) * 64;
    float acc[2][8][4];
    #pragma unroll
    for (int i = 0; i < 2; i++)
        #pragma unroll
        for (int j = 0; j < 8; j++)
            #pragma unroll
            for (int q = 0; q < 4; q++) acc[i][j][q] = 0.f;
    if (tid < 128) ssum[tid] = 0.f;
    int rowt = tid >> 1, kbt = (tid & 1) * 16;
    const float* ap = g_k + (size_t)(b0 + rowt)*Mm + kbt;
    const __nv_bfloat16* bp = g_mbf + (size_t)(n0 + rowt)*Mm + kbt;
    float4 ra0 = *(const float4*)(ap),   ra1 = *(const float4*)(ap+4),
           ra2 = *(const float4*)(ap+8), ra3 = *(const float4*)(ap+12);
    uint4 rb0 = *(const uint4*)(bp), rb1 = *(const uint4*)(bp+8);
    #pragma unroll
    for (int it = 0; it < 4; it++) {
        cvt_store8(&As[rowt*PADK + kbt],     ra0, ra1);
        cvt_store8(&As[rowt*PADK + kbt + 8], ra2, ra3);
        *(uint4*)(&Bs[rowt*PADK + kbt])     = rb0;
        *(uint4*)(&Bs[rowt*PADK + kbt + 8]) = rb1;
        __syncthreads();
        if (it < 3) {
            ap += 32; bp += 32;
            ra0 = *(const float4*)(ap);   ra1 = *(const float4*)(ap+4);
            ra2 = *(const float4*)(ap+8); ra3 = *(const float4*)(ap+12);
            rb0 = *(const uint4*)(bp); rb1 = *(const uint4*)(bp+8);
        }
        #pragma unroll
        for (int kk = 0; kk < 32; kk += 16) {
            unsigned af[2][4], bf[4][4];
            #pragma unroll
            for (int i = 0; i < 2; i++)
                ldsm4(af[i], &As[(wm + i*16 + (lane & 15))*PADK + kk + (lane >> 4)*8]);
            #pragma unroll
            for (int j = 0; j < 4; j++)
                ldsm4(bf[j], &Bs[(wn + j*16 + (lane & 7) + ((lane >> 4) & 1)*8)*PADK
                                  + kk + ((lane >> 3) & 1)*8]);
            #pragma unroll
            for (int i = 0; i < 2; i++)
                #pragma unroll
                for (int j = 0; j < 4; j++) {
                    mma16816(acc[i][2*j],   af[i], &bf[j][0]);
                    mma16816(acc[i][2*j+1], af[i], &bf[j][2]);
                }
        }
        __syncthreads();
    }
    int r4 = lane >> 2, c2 = (lane & 3)*2;
    #pragma unroll
    for (int i = 0; i < 2; i++) {
        #pragma unroll
        for (int rs = 0; rs < 2; rs++) {
            int bl = wm + i*16 + rs*8 + r4;
            int bg = b0 + bl;
            float be2 = g_beta[bg] * 1.44269504f * g_nk[bg];
            float rsum = 0.f;
            #pragma unroll
            for (int j8 = 0; j8 < 8; j8++) {
                int ng0 = n0 + wn + j8*8 + c2;
                float v0 = fast_exp2(be2 * acc[i][j8][rs*2]   * g_nm[ng0]);
                float v1 = fast_exp2(be2 * acc[i][j8][rs*2+1] * g_nm[ng0+1]);
                *(float2*)(g_t + (size_t)bg*Nn + ng0) = make_float2(v0, v1);
                rsum += v0 + v1;
            }
            atomicAdd(&ssum[bl], rsum);
        }
    }
    __syncthreads();
    if (tid < 128) atomicAdd(&g_sum[b0 + tid], ssum[tid]);
}

// ---------------- kernel 4: head weight updates (8 floats/thread, b-split) ----------------
__global__ __launch_bounds__(256) void heads5_kernel(
    const float* __restrict__ wr, const float* __restrict__ ww,
    float* __restrict__ wr_t, float* __restrict__ ww_t, int b_off)
{
    int b = blockIdx.y + b_off;
    int n = blockIdx.x * 2048 + threadIdx.x * 8;
    int lane = threadIdx.x & 31;
    float inv = 1.f / g_sum[b];
    float g = g_gate[b], omg = 1.f - g;
    float s0 = g_s[b*Ss+0], s1 = g_s[b*Ss+1], s2 = g_s[b*Ss+2];
    const float* gt = g_t + (size_t)b * Nn;

    const float* prev[5]; float* outp[5];
    prev[0] = ww + (size_t)b*Nn; outp[0] = ww_t + (size_t)b*Nn;
    #pragma unroll
    for (int hd = 1; hd < 5; hd++) {
        size_t off = ((size_t)(hd-1)*Bb + b) * Nn;
        prev[hd] = wr + off; outp[hd] = wr_t + off;
    }
    float4 wa = *(const float4*)(gt + n);
    float4 wb = *(const float4*)(gt + n + 4);
    float4 pa[5], pb[5];
    #pragma unroll
    for (int hd = 0; hd < 5; hd++) {
        pa[hd] = *(const float4*)(prev[hd] + n);
        pb[hd] = *(const float4*)(prev[hd] + n + 4);
    }
    float wcv[10];
    wcv[1]=wa.x*inv; wcv[2]=wa.y*inv; wcv[3]=wa.z*inv; wcv[4]=wa.w*inv;
    wcv[5]=wb.x*inv; wcv[6]=wb.y*inv; wcv[7]=wb.z*inv; wcv[8]=wb.w*inv;
    wcv[0] = __shfl_up_sync(0xffffffffu, wcv[8], 1);
    wcv[9] = __shfl_down_sync(0xffffffffu, wcv[1], 1);
    float pl[5], pr[5];
    #pragma unroll
    for (int hd = 0; hd < 5; hd++) {
        pl[hd] = __shfl_up_sync(0xffffffffu, pb[hd].w, 1);
        pr[hd] = __shfl_down_sync(0xffffffffu, pa[hd].x, 1);
    }
    if (lane == 0) {
        int nl = (n - 1 + Nn) & (Nn - 1);
        wcv[0] = gt[nl] * inv;
        #pragma unroll
        for (int hd = 0; hd < 5; hd++) pl[hd] = __ldg(prev[hd] + nl);
    }
    if (lane == 31) {
        int nr = (n + 8) & (Nn - 1);
        wcv[9] = gt[nr] * inv;
        #pragma unroll
        for (int hd = 0; hd < 5; hd++) pr[hd] = __ldg(prev[hd] + nr);
    }
    #pragma unroll
    for (int hd = 0; hd < 5; hd++) {
        float pv[10];
        pv[0]=pl[hd];
        pv[1]=pa[hd].x; pv[2]=pa[hd].y; pv[3]=pa[hd].z; pv[4]=pa[hd].w;
        pv[5]=pb[hd].x; pv[6]=pb[hd].y; pv[7]=pb[hd].z; pv[8]=pb[hd].w;
        pv[9]=pr[hd];
        float wg[10];
        #pragma unroll
        for (int q = 0; q < 10; q++) wg[q] = fmaf(g, wcv[q], omg*pv[q]);
        float4 oa, ob;
        oa.x = s0*wg[2] + s1*wg[1] + s2*wg[0];
        oa.y = s0*wg[3] + s1*wg[2] + s2*wg[1];
        oa.z = s0*wg[4] + s1*wg[3] + s2*wg[2];
        oa.w = s0*wg[5] + s1*wg[4] + s2*wg[3];
        ob.x = s0*wg[6] + s1*wg[5] + s2*wg[4];
        ob.y = s0*wg[7] + s1*wg[6] + s2*wg[5];
        ob.z = s0*wg[8] + s1*wg[7] + s2*wg[6];
        ob.w = s0*wg[9] + s1*wg[8] + s2*wg[7];
        *(float4*)(outp[hd] + n)     = oa;
        *(float4*)(outp[hd] + n + 4) = ob;
    }
}

// ---------------- kernel 5: fused erase+add GEMM + m_t epilogue ----------------
__global__ __launch_bounds__(256) void memfused_hmma(
    const float* __restrict__ ww, const float* __restrict__ m, float* __restrict__ m_t)
{
    __shared__ __align__(16) __nv_bfloat16 As[32*PAD64];
    __shared__ __align__(16) __nv_bfloat16 Be[32*PADW];
    __shared__ __align__(16) __nv_bfloat16 Ba[32*PADW];
    int tid = threadIdx.x, lane = tid & 31, w = tid >> 5;
    int n0 = blockIdx.x * 64;
    int wm = (w >> 2) * 32, wn = (w & 3) * 32;
    float ae[2][4][4], aa[2][4][4];
    #pragma unroll
    for (int i = 0; i < 2; i++)
        #pragma unroll
        for (int j = 0; j < 4; j++)
            #pragma unroll
            for (int q = 0; q < 4; q++) { ae[i][j][q] = 0.f; aa[i][j][q] = 0.f; }
    int arw = tid >> 3, acl = (tid & 7) * 8;
    int brw = tid >> 3, bcl = (tid & 7) * 16;
    for (int bc = 0; bc < Bb; bc += 32) {
        const float* apw = ww + (size_t)(bc + arw)*Nn + n0 + acl;
        float4 a0 = *(const float4*)(apw), a1 = *(const float4*)(apw+4);
        cvt_store8(&As[arw*PAD64 + acl], a0, a1);
        const float* ep = g_e + (size_t)(bc + brw)*Mm + bcl;
        float4 e0 = *(const float4*)(ep),   e1 = *(const float4*)(ep+4),
               e2 = *(const float4*)(ep+8), e3 = *(const float4*)(ep+12);
        cvt_store8(&Be[brw*PADW + bcl],     e0, e1);
        cvt_store8(&Be[brw*PADW + bcl + 8], e2, e3);
        const float* apb = g_a + (size_t)(bc + brw)*Mm + bcl;
        float4 f0 = *(const float4*)(apb),   f1 = *(const float4*)(apb+4),
               f2 = *(const float4*)(apb+8), f3 = *(const float4*)(apb+12);
        cvt_store8(&Ba[brw*PADW + bcl],     f0, f1);
        cvt_store8(&Ba[brw*PADW + bcl + 8], f2, f3);
        __syncthreads();
        #pragma unroll
        for (int kk = 0; kk < 32; kk += 16) {
            unsigned af[2][4], bfe[2][4], bfa[2][4];
            #pragma unroll
            for (int i = 0; i < 2; i++)
                ldsm4t(af[i], &As[(kk + (lane & 7) + ((lane >> 4) & 1)*8)*PAD64
                                   + wm + i*16 + ((lane >> 3) & 1)*8]);
            #pragma unroll
            for (int j = 0; j < 2; j++) {
                ldsm4t(bfe[j], &Be[(kk + (lane & 15))*PADW + wn + j*16 + (lane >> 4)*8]);
                ldsm4t(bfa[j], &Ba[(kk + (lane & 15))*PADW + wn + j*16 + (lane >> 4)*8]);
            }
            #pragma unroll
            for (int i = 0; i < 2; i++)
                #pragma unroll
                for (int j = 0; j < 2; j++) {
                    mma16816(ae[i][2*j],   af[i], &bfe[j][0]);
                    mma16816(ae[i][2*j+1], af[i], &bfe[j][2]);
                    mma16816(aa[i][2*j],   af[i], &bfa[j][0]);
                    mma16816(aa[i][2*j+1], af[i], &bfa[j][2]);
                }
        }
        __syncthreads();
    }
    int r4 = lane >> 2, c2 = (lane & 3)*2;
    #pragma unroll
    for (int i = 0; i < 2; i++) {
        #pragma unroll
        for (int j8 = 0; j8 < 4; j8++) {
            int col = wn + j8*8 + c2;
            #pragma unroll
            for (int rs = 0; rs < 2; rs++) {
                int row = n0 + wm + i*16 + rs*8 + r4;
                float me0 = ae[i][j8][rs*2], me1 = ae[i][j8][rs*2+1];
                float ma0 = aa[i][j8][rs*2], ma1 = aa[i][j8][rs*2+1];
                float2 mv = *(const float2*)(m + (size_t)row*Mm + col);
                float2 o;
                o.x = mv.x * (1.f - me0) + ma0;
                o.y = mv.y * (1.f - me1) + ma1;
                *(float2*)(m_t + (size_t)row*Mm + col) = o;
            }
        }
    }
}

// ---------------- kernel 6: r_t GEMM v5 (TF32, no conversions, split-K=16) ----------------
// 64m x 128n tile, K-chunk 32, double-buffered fp32 smem (dynamic, 52KB).
__global__ __launch_bounds__(256, 2) void rt_tf32(
    const float* __restrict__ wr, const float* __restrict__ m, float* __restrict__ r_out)
{
    extern __shared__ float sm[];
    float* Abuf = sm;                      // 2 x 64*PADA
    float* Bbuf = sm + 2*64*PADA;          // 2 x 32*PADB
    int tid = threadIdx.x, lane = tid & 31, w = tid >> 5;
    int g4 = lane >> 2, tq = lane & 3;
    int row0 = blockIdx.x * 64;
    int kb = blockIdx.y * 1024;
    int wm = (w >> 2) * 32, wn = (w & 3) * 32;
    float acc[2][4][4];
    #pragma unroll
    for (int i = 0; i < 2; i++)
        #pragma unroll
        for (int j = 0; j < 4; j++)
            #pragma unroll
            for (int q = 0; q < 4; q++) acc[i][j][q] = 0.f;
    int arow = tid >> 2, acol = (tid & 3) * 8;     // A: 64r x 32k, 8 floats/thr
    int brow = tid >> 3, bcol = (tid & 7) * 16;    // B: 32k x 128n, 16 floats/thr
    const float* aptr = wr + (size_t)(row0 + arow)*Nn + kb + acol;
    const float* bptr = m + (size_t)(kb + brow)*Mm + bcol;
    float4 ra0 = *(const float4*)(aptr), ra1 = *(const float4*)(aptr+4);
    float4 rb0 = *(const float4*)(bptr),   rb1 = *(const float4*)(bptr+4),
           rb2 = *(const float4*)(bptr+8), rb3 = *(const float4*)(bptr+12);
    for (int it = 0; it < 32; it++) {
        float* Ab = Abuf + (it & 1) * (64*PADA);
        float* Bbf = Bbuf + (it & 1) * (32*PADB);
        *(float4*)(Ab + arow*PADA + acol)     = ra0;
        *(float4*)(Ab + arow*PADA + acol + 4) = ra1;
        *(float4*)(Bbf + brow*PADB + bcol)      = rb0;
        *(float4*)(Bbf + brow*PADB + bcol + 4)  = rb1;
        *(float4*)(Bbf + brow*PADB + bcol + 8)  = rb2;
        *(float4*)(Bbf + brow*PADB + bcol + 12) = rb3;
        if (it < 31) {
            aptr += 32; bptr += (size_t)32 * Mm;
            ra0 = *(const float4*)(aptr); ra1 = *(const float4*)(aptr+4);
            rb0 = *(const float4*)(bptr);   rb1 = *(const float4*)(bptr+4);
            rb2 = *(const float4*)(bptr+8); rb3 = *(const float4*)(bptr+12);
        }
        __syncthreads();
        #pragma unroll
        for (int kk = 0; kk < 32; kk += 8) {
            float af[2][4], bf[4][2];
            #pragma unroll
            for (int i = 0; i < 2; i++) {
                const float* base = Ab + (wm + i*16 + g4)*PADA + kk + tq;
                af[i][0] = base[0];
                af[i][1] = base[8*PADA];
                af[i][2] = base[4];
                af[i][3] = base[8*PADA + 4];
            }
            #pragma unroll
            for (int j = 0; j < 4; j++) {
                const float* bb = Bbf + (kk + tq)*PADB + wn + j*8 + g4;
                bf[j][0] = bb[0];
                bf[j][1] = bb[4*PADB];
            }
            #pragma unroll
            for (int i = 0; i < 2; i++)
                #pragma unroll
                for (int j = 0; j < 4; j++)
                    mma1688_tf32(acc[i][j], af[i], bf[j]);
        }
    }
    int c2 = tq * 2;
    #pragma unroll
    for (int i = 0; i < 2; i++) {
        #pragma unroll
        for (int rs = 0; rs < 2; rs++) {
            int rb = row0 + wm + i*16 + rs*8 + g4;
            int r = rb >> 9, b = rb & (Bb - 1);
            float* dst = r_out + ((size_t)b*Rr + r)*Mm;
            #pragma unroll
            for (int j = 0; j < 4; j++) {
                int col = wn + j*8 + c2;
                asm volatile("red.global.add.v2.f32 [%0], {%1, %2};"
                    :: "l"(dst + col), "f"(acc[i][j][rs*2]), "f"(acc[i][j][rs*2+1])
                    : "memory");
            }
        }
    }
}

// ---------------- streams/events ----------------
#define RT_SMEM ((2*64*PADA + 2*32*PADB) * 4)
namespace {
struct HostRes {
    cudaStream_t s1, s2;
    cudaEvent_t e0, eC, eM, eS, e1, e2;
    HostRes() {
        cudaStreamCreateWithFlags(&s1, cudaStreamNonBlocking);
        cudaStreamCreateWithFlags(&s2, cudaStreamNonBlocking);
        cudaEventCreateWithFlags(&e0, cudaEventDisableTiming);
        cudaEventCreateWithFlags(&eC, cudaEventDisableTiming);
        cudaEventCreateWithFlags(&eM, cudaEventDisableTiming);
        cudaEventCreateWithFlags(&eS, cudaEventDisableTiming);
        cudaEventCreateWithFlags(&e1, cudaEventDisableTiming);
        cudaEventCreateWithFlags(&e2, cudaEventDisableTiming);
        cudaFuncSetAttribute(rt_tf32, cudaFuncAttributeMaxDynamicSharedMemorySize, RT_SMEM);
    }
};
HostRes g_res;
}

// ---------------- launch ----------------
extern "C" void kernel_launch(void* const* d_in, const int* in_sizes, int n_in,
                              void* d_out, int out_size)
{
    const float* h_t = (const float*)d_in[0];
    const float* wr  = (const float*)d_in[1];
    const float* ww  = (const float*)d_in[2];
    const float* m   = (const float*)d_in[3];
    const float* kw  = (const float*)d_in[4];
    const float* kb  = (const float*)d_in[5];
    const float* bw  = (const float*)d_in[6];
    const float* bbv = (const float*)d_in[7];
    const float* gw  = (const float*)d_in[8];
    const float* gb  = (const float*)d_in[9];
    const float* sw  = (const float*)d_in[10];
    const float* sb  = (const float*)d_in[11];
    const float* ew  = (const float*)d_in[14];
    const float* eb  = (const float*)d_in[15];
    const float* aw  = (const float*)d_in[16];
    const float* ab  = (const float*)d_in[17];

    float* out  = (float*)d_out;
    float* r_t  = out;
    float* wr_t = out + (size_t)Bb*Rr*Mm;
    float* ww_t = wr_t + (size_t)Rr*Bb*Nn;
    float* m_t  = ww_t + (size_t)Bb*Nn;

    cudaEventRecord(g_res.e0, 0);   // root — pulls side streams into capture

    // s1: prep_m (m norms + bf16 copy + zero r_t) -> rt GEMM (tf32)
    cudaStreamWaitEvent(g_res.s1, g_res.e0, 0);
    prep_m_kernel<<<2176, 256, 0, g_res.s1>>>(m, r_t);
    cudaEventRecord(g_res.eM, g_res.s1);
    rt_tf32<<<dim3(2048/64, 16), 256, RT_SMEM, g_res.s1>>>(wr, m, r_t);

    // legacy: ctrl -> prep_k
    ctrl_kernel<<<dim3(Bb/8, 8), 256>>>(h_t, kw, kb, bw, bbv, gw, gb, sw, sb, ew, eb, aw, ab);
    cudaEventRecord(g_res.eC, 0);
    prep_k_kernel<<<Bb/8, 256>>>();

    // s2: memfused after ctrl
    cudaStreamWaitEvent(g_res.s2, g_res.eC, 0);
    memfused_hmma<<<Nn/64, 256, 0, g_res.s2>>>(ww, m, m_t);

    // legacy: sim halves (needs prep_k + prep_m)
    cudaStreamWaitEvent(0, g_res.eM, 0);
    sim_hmma<<<dim3(Nn/128, 2), 256>>>(0);          // b 0..255
    cudaEventRecord(g_res.eS, 0);
    sim_hmma<<<dim3(Nn/128, 2), 256>>>(256);        // b 256..511

    // s2: heads b 0..127 overlaps sim half B
    cudaStreamWaitEvent(g_res.s2, g_res.eS, 0);
    heads5_kernel<<<dim3(Nn/2048, 128), 256, 0, g_res.s2>>>(wr, ww, wr_t, ww_t, 0);
    cudaEventRecord(g_res.e2, g_res.s2);

    // s1: heads b 128..255 after rt (also needs simA)
    cudaStreamWaitEvent(g_res.s1, g_res.eS, 0);
    heads5_kernel<<<dim3(Nn/2048, 128), 256, 0, g_res.s1>>>(wr, ww, wr_t, ww_t, 128);
    cudaEventRecord(g_res.e1, g_res.s1);

    // legacy: heads b 256..511
    heads5_kernel<<<dim3(Nn/2048, 256), 256>>>(wr, ww, wr_t, ww_t, 256);

    cudaStreamWaitEvent(0, g_res.e1, 0);
    cudaStreamWaitEvent(0, g_res.e2, 0);
}

// round 11
// speedup vs baseline: 1.2830x; 1.2830x over previous
#include <cuda_runtime.h>
#include <cuda_bf16.h>

#define Bb 512
#define Hh 1024
#define Nn 16384
#define Mm 128
#define Rr 4
#define Ss 3

#define PADK 40
#define PADW 136
#define PAD64 72

// ---------------- scratch ----------------
__device__ __align__(16) float g_k[Bb*Mm];
__device__ __align__(16) float g_e[Bb*Mm];
__device__ __align__(16) float g_a[Bb*Mm];
__device__ float g_beta[Bb], g_gate[Bb], g_slog[Bb*Ss], g_s[Bb*Ss];
__device__ float g_nk[Bb], g_nm[Nn], g_sum[Bb];   // INVERSE norms
__device__ __align__(16) float g_t[(size_t)Bb*Nn];
__device__ __align__(16) __nv_bfloat16 g_mbf[(size_t)Nn*Mm];  // bf16 copy of m

// ---------------- helpers ----------------
__device__ __forceinline__ void ldsm4(unsigned* r, const __nv_bfloat16* p) {
    unsigned a = (unsigned)__cvta_generic_to_shared(p);
    asm volatile("ldmatrix.sync.aligned.m8n8.x4.shared.b16 {%0,%1,%2,%3}, [%4];"
        : "=r"(r[0]), "=r"(r[1]), "=r"(r[2]), "=r"(r[3]) : "r"(a));
}
__device__ __forceinline__ void ldsm4t(unsigned* r, const __nv_bfloat16* p) {
    unsigned a = (unsigned)__cvta_generic_to_shared(p);
    asm volatile("ldmatrix.sync.aligned.m8n8.x4.trans.shared.b16 {%0,%1,%2,%3}, [%4];"
        : "=r"(r[0]), "=r"(r[1]), "=r"(r[2]), "=r"(r[3]) : "r"(a));
}
__device__ __forceinline__ void mma16816(float* c, const unsigned* a, const unsigned* b) {
    asm volatile("mma.sync.aligned.m16n8k16.row.col.f32.bf16.bf16.f32 "
        "{%0,%1,%2,%3}, {%4,%5,%6,%7}, {%8,%9}, {%0,%1,%2,%3};"
        : "+f"(c[0]), "+f"(c[1]), "+f"(c[2]), "+f"(c[3])
        : "r"(a[0]), "r"(a[1]), "r"(a[2]), "r"(a[3]), "r"(b[0]), "r"(b[1]));
}
__device__ __forceinline__ void cvt_store8(__nv_bfloat16* dst, float4 v0, float4 v1) {
    __nv_bfloat162* d = (__nv_bfloat162*)dst;
    d[0] = __float22bfloat162_rn(make_float2(v0.x, v0.y));
    d[1] = __float22bfloat162_rn(make_float2(v0.z, v0.w));
    d[2] = __float22bfloat162_rn(make_float2(v1.x, v1.y));
    d[3] = __float22bfloat162_rn(make_float2(v1.z, v1.w));
}
// exp2 on the FMA pipe — no MUFU.
__device__ __forceinline__ float fast_exp2(float x) {
    float t = x + 12582912.0f;
    int ri = __float_as_int(t) - 0x4B400000;
    float f = x - (t - 12582912.0f);
    float p = 0.0013333558f;
    p = fmaf(p, f, 0.0096181298f);
    p = fmaf(p, f, 0.0555041087f);
    p = fmaf(p, f, 0.2402265070f);
    p = fmaf(p, f, 0.6931471806f);
    p = fmaf(p, f, 1.0f);
    return __int_as_float(__float_as_int(p) + (ri << 23));
}

// ---------------- kernel 1: controller projections (8x j-parallel) ----------------
__global__ __launch_bounds__(256) void ctrl_kernel(
    const float* __restrict__ h,
    const float* __restrict__ kw, const float* __restrict__ kb,
    const float* __restrict__ bw, const float* __restrict__ bbv,
    const float* __restrict__ gw, const float* __restrict__ gb,
    const float* __restrict__ sw, const float* __restrict__ sb,
    const float* __restrict__ ew, const float* __restrict__ eb,
    const float* __restrict__ aw, const float* __restrict__ ab)
{
    __shared__ float h_s[8][Hh];
    int b0 = blockIdx.x * 8;
    for (int i = threadIdx.x; i < 8*Hh; i += 256)
        h_s[i >> 10][i & 1023] = h[(size_t)(b0 + (i >> 10))*Hh + (i & 1023)];
    __syncthreads();
    int warp = threadIdx.x >> 5, lane = threadIdx.x & 31;
    for (int j = blockIdx.y*8 + warp; j < 3*Mm + 5; j += 64) {
        const float* wrow; float bias; int act;
        if (j < Mm)        { wrow = kw + (size_t)j*Hh;        bias = kb[j];      act = 0; }
        else if (j < 2*Mm) { wrow = ew + (size_t)(j-Mm)*Hh;   bias = eb[j-Mm];   act = 0; }
        else if (j < 3*Mm) { wrow = aw + (size_t)(j-2*Mm)*Hh; bias = ab[j-2*Mm]; act = 0; }
        else if (j == 384) { wrow = bw;                       bias = bbv[0];     act = 2; }
        else if (j == 385) { wrow = gw;                       bias = gb[0];      act = 0; }
        else               { wrow = sw + (size_t)(j-386)*Hh;  bias = sb[j-386];  act = 3; }
        float acc[8];
        #pragma unroll
        for (int q = 0; q < 8; q++) acc[q] = 0.f;
        for (int k = lane; k < Hh; k += 32) {
            float wv = __ldg(wrow + k);
            #pragma unroll
            for (int q = 0; q < 8; q++) acc[q] = fmaf(wv, h_s[q][k], acc[q]);
        }
        #pragma unroll
        for (int q = 0; q < 8; q++) {
            float v = acc[q];
            #pragma unroll
            for (int o = 16; o; o >>= 1) v += __shfl_down_sync(0xffffffffu, v, o);
            if (lane == 0) {
                v += bias;
                if (act == 0) v = fminf(fmaxf(v, 0.f), 1.f);
                else if (act == 2) v = fmaxf(v, 0.f);
                int b = b0 + q;
                if (j < Mm)        g_k[b*Mm + j] = v;
                else if (j < 2*Mm) g_e[b*Mm + (j-Mm)] = v;
                else if (j < 3*Mm) g_a[b*Mm + (j-2*Mm)] = v;
                else if (j == 384) g_beta[b] = v;
                else if (j == 385) g_gate[b] = v;
                else               g_slog[b*Ss + (j-386)] = v;
            }
        }
    }
}

// ---------------- kernel 2a: m inverse norms + bf16 copy + zero r_t ----------------
__global__ __launch_bounds__(256) void prep_m_kernel(const float* __restrict__ m, float* __restrict__ r_out)
{
    int warp = threadIdx.x >> 5, lane = threadIdx.x & 31;
    int bidx = blockIdx.x;
    if (bidx < 2048) {
        int n = bidx*8 + warp;
        float4 v = *(const float4*)(m + (size_t)n*Mm + lane*4);
        __nv_bfloat162* dst = (__nv_bfloat162*)(g_mbf + (size_t)n*Mm + lane*4);
        dst[0] = __float22bfloat162_rn(make_float2(v.x, v.y));
        dst[1] = __float22bfloat162_rn(make_float2(v.z, v.w));
        float ss = v.x*v.x + v.y*v.y + v.z*v.z + v.w*v.w;
        #pragma unroll
        for (int o = 16; o; o >>= 1) ss += __shfl_down_sync(0xffffffffu, ss, o);
        if (lane == 0) g_nm[n] = (ss > 0.f) ? 1.f/sqrtf(ss) : 0.f;
    } else {
        int base = (bidx-2048)*2048 + threadIdx.x*8;
        float4 z = make_float4(0.f,0.f,0.f,0.f);
        *(float4*)(r_out + base)     = z;
        *(float4*)(r_out + base + 4) = z;
    }
}

// ---------------- kernel 2b: k inverse norms + shift softmax ----------------
__global__ __launch_bounds__(256) void prep_k_kernel()
{
    int warp = threadIdx.x >> 5, lane = threadIdx.x & 31;
    int b = blockIdx.x*8 + warp;
    float4 v = *(const float4*)(g_k + (size_t)b*Mm + lane*4);
    float ss = v.x*v.x + v.y*v.y + v.z*v.z + v.w*v.w;
    #pragma unroll
    for (int o = 16; o; o >>= 1) ss += __shfl_down_sync(0xffffffffu, ss, o);
    if (lane == 0) {
        g_nk[b] = (ss > 0.f) ? 1.f/sqrtf(ss) : 0.f;
        g_sum[b] = 0.f;
        float x0 = g_slog[b*Ss+0], x1 = g_slog[b*Ss+1], x2 = g_slog[b*Ss+2];
        float mx = fmaxf(x0, fmaxf(x1, x2));
        float e0 = expf(x0-mx), e1 = expf(x1-mx), e2 = expf(x2-mx);
        float it = 1.f / (e0+e1+e2);
        g_s[b*Ss+0] = e0*it; g_s[b*Ss+1] = e1*it; g_s[b*Ss+2] = e2*it;
    }
}

// ---------------- kernel 3: sim GEMM (double-buffered, 1 barrier/iter) ----------------
__global__ __launch_bounds__(256) void sim_hmma(int b_off)
{
    __shared__ __align__(16) __nv_bfloat16 As[2][128*PADK];
    __shared__ __align__(16) __nv_bfloat16 Bs[2][128*PADK];
    __shared__ float ssum[128];
    int tid = threadIdx.x, lane = tid & 31, w = tid >> 5;
    int n0 = blockIdx.x * 128, b0 = blockIdx.y * 128 + b_off;
    int wm = (w >> 1) * 32, wn = (w & 1) * 64;
    float acc[2][8][4];
    #pragma unroll
    for (int i = 0; i < 2; i++)
        #pragma unroll
        for (int j = 0; j < 8; j++)
            #pragma unroll
            for (int q = 0; q < 4; q++) acc[i][j][q] = 0.f;
    if (tid < 128) ssum[tid] = 0.f;
    int rowt = tid >> 1, kbt = (tid & 1) * 16;
    const float* ap = g_k + (size_t)(b0 + rowt)*Mm + kbt;
    const __nv_bfloat16* bp = g_mbf + (size_t)(n0 + rowt)*Mm + kbt;
    float4 ra0 = *(const float4*)(ap),   ra1 = *(const float4*)(ap+4),
           ra2 = *(const float4*)(ap+8), ra3 = *(const float4*)(ap+12);
    uint4 rb0 = *(const uint4*)(bp), rb1 = *(const uint4*)(bp+8);
    #pragma unroll
    for (int it = 0; it < 4; it++) {
        __nv_bfloat16* Ab = As[it & 1];
        __nv_bfloat16* Bbf = Bs[it & 1];
        cvt_store8(&Ab[rowt*PADK + kbt],     ra0, ra1);
        cvt_store8(&Ab[rowt*PADK + kbt + 8], ra2, ra3);
        *(uint4*)(&Bbf[rowt*PADK + kbt])     = rb0;
        *(uint4*)(&Bbf[rowt*PADK + kbt + 8]) = rb1;
        if (it < 3) {
            ap += 32; bp += 32;
            ra0 = *(const float4*)(ap);   ra1 = *(const float4*)(ap+4);
            ra2 = *(const float4*)(ap+8); ra3 = *(const float4*)(ap+12);
            rb0 = *(const uint4*)(bp); rb1 = *(const uint4*)(bp+8);
        }
        __syncthreads();                   // single barrier per iteration
        #pragma unroll
        for (int kk = 0; kk < 32; kk += 16) {
            unsigned af[2][4], bf[4][4];
            #pragma unroll
            for (int i = 0; i < 2; i++)
                ldsm4(af[i], &Ab[(wm + i*16 + (lane & 15))*PADK + kk + (lane >> 4)*8]);
            #pragma unroll
            for (int j = 0; j < 4; j++)
                ldsm4(bf[j], &Bbf[(wn + j*16 + (lane & 7) + ((lane >> 4) & 1)*8)*PADK
                                  + kk + ((lane >> 3) & 1)*8]);
            #pragma unroll
            for (int i = 0; i < 2; i++)
                #pragma unroll
                for (int j = 0; j < 4; j++) {
                    mma16816(acc[i][2*j],   af[i], &bf[j][0]);
                    mma16816(acc[i][2*j+1], af[i], &bf[j][2]);
                }
        }
    }
    int r4 = lane >> 2, c2 = (lane & 3)*2;
    #pragma unroll
    for (int i = 0; i < 2; i++) {
        #pragma unroll
        for (int rs = 0; rs < 2; rs++) {
            int bl = wm + i*16 + rs*8 + r4;
            int bg = b0 + bl;
            float be2 = g_beta[bg] * 1.44269504f * g_nk[bg];
            float rsum = 0.f;
            #pragma unroll
            for (int j8 = 0; j8 < 8; j8++) {
                int ng0 = n0 + wn + j8*8 + c2;
                float v0 = fast_exp2(be2 * acc[i][j8][rs*2]   * g_nm[ng0]);
                float v1 = fast_exp2(be2 * acc[i][j8][rs*2+1] * g_nm[ng0+1]);
                *(float2*)(g_t + (size_t)bg*Nn + ng0) = make_float2(v0, v1);
                rsum += v0 + v1;
            }
            atomicAdd(&ssum[bl], rsum);
        }
    }
    __syncthreads();
    if (tid < 128) atomicAdd(&g_sum[b0 + tid], ssum[tid]);
}

// ---------------- kernel 4: head weight updates (8 floats/thread, b-split) ----------------
__global__ __launch_bounds__(256) void heads5_kernel(
    const float* __restrict__ wr, const float* __restrict__ ww,
    float* __restrict__ wr_t, float* __restrict__ ww_t, int b_off)
{
    int b = blockIdx.y + b_off;
    int n = blockIdx.x * 2048 + threadIdx.x * 8;
    int lane = threadIdx.x & 31;
    float inv = 1.f / g_sum[b];
    float g = g_gate[b], omg = 1.f - g;
    float s0 = g_s[b*Ss+0], s1 = g_s[b*Ss+1], s2 = g_s[b*Ss+2];
    const float* gt = g_t + (size_t)b * Nn;

    const float* prev[5]; float* outp[5];
    prev[0] = ww + (size_t)b*Nn; outp[0] = ww_t + (size_t)b*Nn;
    #pragma unroll
    for (int hd = 1; hd < 5; hd++) {
        size_t off = ((size_t)(hd-1)*Bb + b) * Nn;
        prev[hd] = wr + off; outp[hd] = wr_t + off;
    }
    float4 wa = *(const float4*)(gt + n);
    float4 wb = *(const float4*)(gt + n + 4);
    float4 pa[5], pb[5];
    #pragma unroll
    for (int hd = 0; hd < 5; hd++) {
        pa[hd] = *(const float4*)(prev[hd] + n);
        pb[hd] = *(const float4*)(prev[hd] + n + 4);
    }
    float wcv[10];
    wcv[1]=wa.x*inv; wcv[2]=wa.y*inv; wcv[3]=wa.z*inv; wcv[4]=wa.w*inv;
    wcv[5]=wb.x*inv; wcv[6]=wb.y*inv; wcv[7]=wb.z*inv; wcv[8]=wb.w*inv;
    wcv[0] = __shfl_up_sync(0xffffffffu, wcv[8], 1);
    wcv[9] = __shfl_down_sync(0xffffffffu, wcv[1], 1);
    float pl[5], pr[5];
    #pragma unroll
    for (int hd = 0; hd < 5; hd++) {
        pl[hd] = __shfl_up_sync(0xffffffffu, pb[hd].w, 1);
        pr[hd] = __shfl_down_sync(0xffffffffu, pa[hd].x, 1);
    }
    if (lane == 0) {
        int nl = (n - 1 + Nn) & (Nn - 1);
        wcv[0] = gt[nl] * inv;
        #pragma unroll
        for (int hd = 0; hd < 5; hd++) pl[hd] = __ldg(prev[hd] + nl);
    }
    if (lane == 31) {
        int nr = (n + 8) & (Nn - 1);
        wcv[9] = gt[nr] * inv;
        #pragma unroll
        for (int hd = 0; hd < 5; hd++) pr[hd] = __ldg(prev[hd] + nr);
    }
    #pragma unroll
    for (int hd = 0; hd < 5; hd++) {
        float pv[10];
        pv[0]=pl[hd];
        pv[1]=pa[hd].x; pv[2]=pa[hd].y; pv[3]=pa[hd].z; pv[4]=pa[hd].w;
        pv[5]=pb[hd].x; pv[6]=pb[hd].y; pv[7]=pb[hd].z; pv[8]=pb[hd].w;
        pv[9]=pr[hd];
        float wg[10];
        #pragma unroll
        for (int q = 0; q < 10; q++) wg[q] = fmaf(g, wcv[q], omg*pv[q]);
        float4 oa, ob;
        oa.x = s0*wg[2] + s1*wg[1] + s2*wg[0];
        oa.y = s0*wg[3] + s1*wg[2] + s2*wg[1];
        oa.z = s0*wg[4] + s1*wg[3] + s2*wg[2];
        oa.w = s0*wg[5] + s1*wg[4] + s2*wg[3];
        ob.x = s0*wg[6] + s1*wg[5] + s2*wg[4];
        ob.y = s0*wg[7] + s1*wg[6] + s2*wg[5];
        ob.z = s0*wg[8] + s1*wg[7] + s2*wg[6];
        ob.w = s0*wg[9] + s1*wg[8] + s2*wg[7];
        *(float4*)(outp[hd] + n)     = oa;
        *(float4*)(outp[hd] + n + 4) = ob;
    }
}

// ---------------- kernel 5: fused erase+add GEMM + m_t epilogue ----------------
__global__ __launch_bounds__(256) void memfused_hmma(
    const float* __restrict__ ww, const float* __restrict__ m, float* __restrict__ m_t)
{
    __shared__ __align__(16) __nv_bfloat16 As[32*PAD64];
    __shared__ __align__(16) __nv_bfloat16 Be[32*PADW];
    __shared__ __align__(16) __nv_bfloat16 Ba[32*PADW];
    int tid = threadIdx.x, lane = tid & 31, w = tid >> 5;
    int n0 = blockIdx.x * 64;
    int wm = (w >> 2) * 32, wn = (w & 3) * 32;
    float ae[2][4][4], aa[2][4][4];
    #pragma unroll
    for (int i = 0; i < 2; i++)
        #pragma unroll
        for (int j = 0; j < 4; j++)
            #pragma unroll
            for (int q = 0; q < 4; q++) { ae[i][j][q] = 0.f; aa[i][j][q] = 0.f; }
    int arw = tid >> 3, acl = (tid & 7) * 8;
    int brw = tid >> 3, bcl = (tid & 7) * 16;
    for (int bc = 0; bc < Bb; bc += 32) {
        const float* apw = ww + (size_t)(bc + arw)*Nn + n0 + acl;
        float4 a0 = *(const float4*)(apw), a1 = *(const float4*)(apw+4);
        cvt_store8(&As[arw*PAD64 + acl], a0, a1);
        const float* ep = g_e + (size_t)(bc + brw)*Mm + bcl;
        float4 e0 = *(const float4*)(ep),   e1 = *(const float4*)(ep+4),
               e2 = *(const float4*)(ep+8), e3 = *(const float4*)(ep+12);
        cvt_store8(&Be[brw*PADW + bcl],     e0, e1);
        cvt_store8(&Be[brw*PADW + bcl + 8], e2, e3);
        const float* apb = g_a + (size_t)(bc + brw)*Mm + bcl;
        float4 f0 = *(const float4*)(apb),   f1 = *(const float4*)(apb+4),
               f2 = *(const float4*)(apb+8), f3 = *(const float4*)(apb+12);
        cvt_store8(&Ba[brw*PADW + bcl],     f0, f1);
        cvt_store8(&Ba[brw*PADW + bcl + 8], f2, f3);
        __syncthreads();
        #pragma unroll
        for (int kk = 0; kk < 32; kk += 16) {
            unsigned af[2][4], bfe[2][4], bfa[2][4];
            #pragma unroll
            for (int i = 0; i < 2; i++)
                ldsm4t(af[i], &As[(kk + (lane & 7) + ((lane >> 4) & 1)*8)*PAD64
                                   + wm + i*16 + ((lane >> 3) & 1)*8]);
            #pragma unroll
            for (int j = 0; j < 2; j++) {
                ldsm4t(bfe[j], &Be[(kk + (lane & 15))*PADW + wn + j*16 + (lane >> 4)*8]);
                ldsm4t(bfa[j], &Ba[(kk + (lane & 15))*PADW + wn + j*16 + (lane >> 4)*8]);
            }
            #pragma unroll
            for (int i = 0; i < 2; i++)
                #pragma unroll
                for (int j = 0; j < 2; j++) {
                    mma16816(ae[i][2*j],   af[i], &bfe[j][0]);
                    mma16816(ae[i][2*j+1], af[i], &bfe[j][2]);
                    mma16816(aa[i][2*j],   af[i], &bfa[j][0]);
                    mma16816(aa[i][2*j+1], af[i], &bfa[j][2]);
                }
        }
        __syncthreads();
    }
    int r4 = lane >> 2, c2 = (lane & 3)*2;
    #pragma unroll
    for (int i = 0; i < 2; i++) {
        #pragma unroll
        for (int j8 = 0; j8 < 4; j8++) {
            int col = wn + j8*8 + c2;
            #pragma unroll
            for (int rs = 0; rs < 2; rs++) {
                int row = n0 + wm + i*16 + rs*8 + r4;
                float me0 = ae[i][j8][rs*2], me1 = ae[i][j8][rs*2+1];
                float ma0 = aa[i][j8][rs*2], ma1 = aa[i][j8][rs*2+1];
                float2 mv = *(const float2*)(m + (size_t)row*Mm + col);
                float2 o;
                o.x = mv.x * (1.f - me0) + ma0;
                o.y = mv.y * (1.f - me1) + ma1;
                *(float2*)(m_t + (size_t)row*Mm + col) = o;
            }
        }
    }
}

// ---------------- kernel 6: r_t GEMM (bf16, split-K=16, red.v2) ----------------
__global__ __launch_bounds__(256, 2) void rt_hmma4(
    const float* __restrict__ wr, float* __restrict__ r_out)
{
    __shared__ __align__(16) __nv_bfloat16 As[2][64*PADK];
    __shared__ __align__(16) __nv_bfloat16 Bs[2][32*PADW];
    int tid = threadIdx.x, lane = tid & 31, w = tid >> 5;
    int row0 = blockIdx.x * 64;
    int kb = blockIdx.y * 1024;
    int wm = (w >> 2) * 32, wn = (w & 3) * 32;
    float acc[2][4][4];
    #pragma unroll
    for (int i = 0; i < 2; i++)
        #pragma unroll
        for (int j = 0; j < 4; j++)
            #pragma unroll
            for (int q = 0; q < 4; q++) acc[i][j][q] = 0.f;
    int arow = tid >> 2, akb = (tid & 3) * 8;
    int brow = tid >> 3, bnb = (tid & 7) * 16;
    const float* aptr = wr + (size_t)(row0 + arow)*Nn + kb + akb;
    const __nv_bfloat16* bptr = g_mbf + (size_t)(kb + brow)*Mm + bnb;
    float4 ra0 = *(const float4*)(aptr), ra1 = *(const float4*)(aptr+4);
    uint4 rb0 = *(const uint4*)(bptr), rb1 = *(const uint4*)(bptr+8);
    for (int it = 0; it < 32; it++) {
        __nv_bfloat16* Ab = As[it & 1];
        __nv_bfloat16* Bbf = Bs[it & 1];
        cvt_store8(&Ab[arow*PADK + akb], ra0, ra1);
        *(uint4*)(&Bbf[brow*PADW + bnb])     = rb0;
        *(uint4*)(&Bbf[brow*PADW + bnb + 8]) = rb1;
        if (it < 31) {
            aptr += 32; bptr += (size_t)32 * Mm;
            ra0 = *(const float4*)(aptr); ra1 = *(const float4*)(aptr+4);
            rb0 = *(const uint4*)(bptr); rb1 = *(const uint4*)(bptr+8);
        }
        __syncthreads();
        #pragma unroll
        for (int kk = 0; kk < 32; kk += 16) {
            unsigned af[2][4], bf[2][4];
            #pragma unroll
            for (int i = 0; i < 2; i++)
                ldsm4(af[i], &Ab[(wm + i*16 + (lane & 15))*PADK + kk + (lane >> 4)*8]);
            #pragma unroll
            for (int j = 0; j < 2; j++)
                ldsm4t(bf[j], &Bbf[(kk + (lane & 15))*PADW + wn + j*16 + (lane >> 4)*8]);
            #pragma unroll
            for (int i = 0; i < 2; i++)
                #pragma unroll
                for (int j = 0; j < 2; j++) {
                    mma16816(acc[i][2*j],   af[i], &bf[j][0]);
                    mma16816(acc[i][2*j+1], af[i], &bf[j][2]);
                }
        }
    }
    int r4 = lane >> 2, c2 = (lane & 3)*2;
    #pragma unroll
    for (int i = 0; i < 2; i++) {
        #pragma unroll
        for (int rs = 0; rs < 2; rs++) {
            int rb = row0 + wm + i*16 + rs*8 + r4;
            int r = rb >> 9, b = rb & (Bb - 1);
            float* dst = r_out + ((size_t)b*Rr + r)*Mm;
            #pragma unroll
            for (int j8 = 0; j8 < 4; j8++) {
                int col = wn + j8*8 + c2;
                asm volatile("red.global.add.v2.f32 [%0], {%1, %2};"
                    :: "l"(dst + col), "f"(acc[i][j8][rs*2]), "f"(acc[i][j8][rs*2+1])
                    : "memory");
            }
        }
    }
}

// ---------------- streams/events ----------------
namespace {
struct HostRes {
    cudaStream_t s1, s2;
    cudaEvent_t e0, eC, eM, eS, e1, e2;
    HostRes() {
        cudaStreamCreateWithFlags(&s1, cudaStreamNonBlocking);
        cudaStreamCreateWithFlags(&s2, cudaStreamNonBlocking);
        cudaEventCreateWithFlags(&e0, cudaEventDisableTiming);
        cudaEventCreateWithFlags(&eC, cudaEventDisableTiming);
        cudaEventCreateWithFlags(&eM, cudaEventDisableTiming);
        cudaEventCreateWithFlags(&eS, cudaEventDisableTiming);
        cudaEventCreateWithFlags(&e1, cudaEventDisableTiming);
        cudaEventCreateWithFlags(&e2, cudaEventDisableTiming);
    }
};
HostRes g_res;
}

// ---------------- launch ----------------
extern "C" void kernel_launch(void* const* d_in, const int* in_sizes, int n_in,
                              void* d_out, int out_size)
{
    const float* h_t = (const float*)d_in[0];
    const float* wr  = (const float*)d_in[1];
    const float* ww  = (const float*)d_in[2];
    const float* m   = (const float*)d_in[3];
    const float* kw  = (const float*)d_in[4];
    const float* kb  = (const float*)d_in[5];
    const float* bw  = (const float*)d_in[6];
    const float* bbv = (const float*)d_in[7];
    const float* gw  = (const float*)d_in[8];
    const float* gb  = (const float*)d_in[9];
    const float* sw  = (const float*)d_in[10];
    const float* sb  = (const float*)d_in[11];
    const float* ew  = (const float*)d_in[14];
    const float* eb  = (const float*)d_in[15];
    const float* aw  = (const float*)d_in[16];
    const float* ab  = (const float*)d_in[17];

    float* out  = (float*)d_out;
    float* r_t  = out;
    float* wr_t = out + (size_t)Bb*Rr*Mm;
    float* ww_t = wr_t + (size_t)Rr*Bb*Nn;
    float* m_t  = ww_t + (size_t)Bb*Nn;

    cudaEventRecord(g_res.e0, 0);   // root — pulls side streams into capture

    // s1: prep_m -> rt GEMM (bf16)
    cudaStreamWaitEvent(g_res.s1, g_res.e0, 0);
    prep_m_kernel<<<2176, 256, 0, g_res.s1>>>(m, r_t);
    cudaEventRecord(g_res.eM, g_res.s1);
    rt_hmma4<<<dim3(2048/64, 16), 256, 0, g_res.s1>>>(wr, r_t);

    // legacy: ctrl -> prep_k
    ctrl_kernel<<<dim3(Bb/8, 8), 256>>>(h_t, kw, kb, bw, bbv, gw, gb, sw, sb, ew, eb, aw, ab);
    cudaEventRecord(g_res.eC, 0);
    prep_k_kernel<<<Bb/8, 256>>>();

    // s2: memfused after ctrl
    cudaStreamWaitEvent(g_res.s2, g_res.eC, 0);
    memfused_hmma<<<Nn/64, 256, 0, g_res.s2>>>(ww, m, m_t);

    // legacy: sim halves (needs prep_k + prep_m)
    cudaStreamWaitEvent(0, g_res.eM, 0);
    sim_hmma<<<dim3(Nn/128, 2), 256>>>(0);          // b 0..255
    cudaEventRecord(g_res.eS, 0);
    sim_hmma<<<dim3(Nn/128, 2), 256>>>(256);        // b 256..511

    // s2: heads b 0..127 overlaps sim half B
    cudaStreamWaitEvent(g_res.s2, g_res.eS, 0);
    heads5_kernel<<<dim3(Nn/2048, 128), 256, 0, g_res.s2>>>(wr, ww, wr_t, ww_t, 0);
    cudaEventRecord(g_res.e2, g_res.s2);

    // s1: heads b 128..255 after rt (also needs simA)
    cudaStreamWaitEvent(g_res.s1, g_res.eS, 0);
    heads5_kernel<<<dim3(Nn/2048, 128), 256, 0, g_res.s1>>>(wr, ww, wr_t, ww_t, 128);
    cudaEventRecord(g_res.e1, g_res.s1);

    // legacy: heads b 256..511
    heads5_kernel<<<dim3(Nn/2048, 256), 256>>>(wr, ww, wr_t, ww_t, 256);

    cudaStreamWaitEvent(0, g_res.e1, 0);
    cudaStreamWaitEvent(0, g_res.e2, 0);
}

// round 12
// speedup vs baseline: 1.2832x; 1.0001x over previous
#include <cuda_runtime.h>
#include <cuda_bf16.h>

#define Bb 512
#define Hh 1024
#define Nn 16384
#define Mm 128
#define Rr 4
#define Ss 3

#define PADK 40
#define PADW 136
#define PAD64 72

// ---------------- scratch ----------------
__device__ __align__(16) float g_k[Bb*Mm];
__device__ __align__(16) float g_e[Bb*Mm];
__device__ __align__(16) float g_a[Bb*Mm];
__device__ float g_beta[Bb], g_gate[Bb], g_slog[Bb*Ss], g_s[Bb*Ss];
__device__ float g_nk[Bb], g_nm[Nn], g_sum[Bb];   // INVERSE norms
__device__ __align__(16) float g_t[(size_t)Bb*Nn];
__device__ __align__(16) __nv_bfloat16 g_mbf[(size_t)Nn*Mm];  // bf16 copy of m

// ---------------- helpers ----------------
__device__ __forceinline__ void ldsm4(unsigned* r, const __nv_bfloat16* p) {
    unsigned a = (unsigned)__cvta_generic_to_shared(p);
    asm volatile("ldmatrix.sync.aligned.m8n8.x4.shared.b16 {%0,%1,%2,%3}, [%4];"
        : "=r"(r[0]), "=r"(r[1]), "=r"(r[2]), "=r"(r[3]) : "r"(a));
}
__device__ __forceinline__ void ldsm4t(unsigned* r, const __nv_bfloat16* p) {
    unsigned a = (unsigned)__cvta_generic_to_shared(p);
    asm volatile("ldmatrix.sync.aligned.m8n8.x4.trans.shared.b16 {%0,%1,%2,%3}, [%4];"
        : "=r"(r[0]), "=r"(r[1]), "=r"(r[2]), "=r"(r[3]) : "r"(a));
}
__device__ __forceinline__ void mma16816(float* c, const unsigned* a, const unsigned* b) {
    asm volatile("mma.sync.aligned.m16n8k16.row.col.f32.bf16.bf16.f32 "
        "{%0,%1,%2,%3}, {%4,%5,%6,%7}, {%8,%9}, {%0,%1,%2,%3};"
        : "+f"(c[0]), "+f"(c[1]), "+f"(c[2]), "+f"(c[3])
        : "r"(a[0]), "r"(a[1]), "r"(a[2]), "r"(a[3]), "r"(b[0]), "r"(b[1]));
}
__device__ __forceinline__ void cvt_store8(__nv_bfloat16* dst, float4 v0, float4 v1) {
    __nv_bfloat162* d = (__nv_bfloat162*)dst;
    d[0] = __float22bfloat162_rn(make_float2(v0.x, v0.y));
    d[1] = __float22bfloat162_rn(make_float2(v0.z, v0.w));
    d[2] = __float22bfloat162_rn(make_float2(v1.x, v1.y));
    d[3] = __float22bfloat162_rn(make_float2(v1.z, v1.w));
}
// exp2 on the FMA pipe — no MUFU.
__device__ __forceinline__ float fast_exp2(float x) {
    float t = x + 12582912.0f;
    int ri = __float_as_int(t) - 0x4B400000;
    float f = x - (t - 12582912.0f);
    float p = 0.0013333558f;
    p = fmaf(p, f, 0.0096181298f);
    p = fmaf(p, f, 0.0555041087f);
    p = fmaf(p, f, 0.2402265070f);
    p = fmaf(p, f, 0.6931471806f);
    p = fmaf(p, f, 1.0f);
    return __int_as_float(__float_as_int(p) + (ri << 23));
}

// ---------------- kernel 1: controller projections (8x j-parallel) ----------------
__global__ __launch_bounds__(256) void ctrl_kernel(
    const float* __restrict__ h,
    const float* __restrict__ kw, const float* __restrict__ kb,
    const float* __restrict__ bw, const float* __restrict__ bbv,
    const float* __restrict__ gw, const float* __restrict__ gb,
    const float* __restrict__ sw, const float* __restrict__ sb,
    const float* __restrict__ ew, const float* __restrict__ eb,
    const float* __restrict__ aw, const float* __restrict__ ab)
{
    __shared__ float h_s[8][Hh];
    int b0 = blockIdx.x * 8;
    for (int i = threadIdx.x; i < 8*Hh; i += 256)
        h_s[i >> 10][i & 1023] = h[(size_t)(b0 + (i >> 10))*Hh + (i & 1023)];
    __syncthreads();
    int warp = threadIdx.x >> 5, lane = threadIdx.x & 31;
    for (int j = blockIdx.y*8 + warp; j < 3*Mm + 5; j += 64) {
        const float* wrow; float bias; int act;
        if (j < Mm)        { wrow = kw + (size_t)j*Hh;        bias = kb[j];      act = 0; }
        else if (j < 2*Mm) { wrow = ew + (size_t)(j-Mm)*Hh;   bias = eb[j-Mm];   act = 0; }
        else if (j < 3*Mm) { wrow = aw + (size_t)(j-2*Mm)*Hh; bias = ab[j-2*Mm]; act = 0; }
        else if (j == 384) { wrow = bw;                       bias = bbv[0];     act = 2; }
        else if (j == 385) { wrow = gw;                       bias = gb[0];      act = 0; }
        else               { wrow = sw + (size_t)(j-386)*Hh;  bias = sb[j-386];  act = 3; }
        float acc[8];
        #pragma unroll
        for (int q = 0; q < 8; q++) acc[q] = 0.f;
        for (int k = lane; k < Hh; k += 32) {
            float wv = __ldg(wrow + k);
            #pragma unroll
            for (int q = 0; q < 8; q++) acc[q] = fmaf(wv, h_s[q][k], acc[q]);
        }
        #pragma unroll
        for (int q = 0; q < 8; q++) {
            float v = acc[q];
            #pragma unroll
            for (int o = 16; o; o >>= 1) v += __shfl_down_sync(0xffffffffu, v, o);
            if (lane == 0) {
                v += bias;
                if (act == 0) v = fminf(fmaxf(v, 0.f), 1.f);
                else if (act == 2) v = fmaxf(v, 0.f);
                int b = b0 + q;
                if (j < Mm)        g_k[b*Mm + j] = v;
                else if (j < 2*Mm) g_e[b*Mm + (j-Mm)] = v;
                else if (j < 3*Mm) g_a[b*Mm + (j-2*Mm)] = v;
                else if (j == 384) g_beta[b] = v;
                else if (j == 385) g_gate[b] = v;
                else               g_slog[b*Ss + (j-386)] = v;
            }
        }
    }
}

// ---------------- kernel 2a: m inverse norms + bf16 copy + zero r_t ----------------
__global__ __launch_bounds__(256) void prep_m_kernel(const float* __restrict__ m, float* __restrict__ r_out)
{
    int warp = threadIdx.x >> 5, lane = threadIdx.x & 31;
    int bidx = blockIdx.x;
    if (bidx < 2048) {
        int n = bidx*8 + warp;
        float4 v = *(const float4*)(m + (size_t)n*Mm + lane*4);
        __nv_bfloat162* dst = (__nv_bfloat162*)(g_mbf + (size_t)n*Mm + lane*4);
        dst[0] = __float22bfloat162_rn(make_float2(v.x, v.y));
        dst[1] = __float22bfloat162_rn(make_float2(v.z, v.w));
        float ss = v.x*v.x + v.y*v.y + v.z*v.z + v.w*v.w;
        #pragma unroll
        for (int o = 16; o; o >>= 1) ss += __shfl_down_sync(0xffffffffu, ss, o);
        if (lane == 0) g_nm[n] = (ss > 0.f) ? 1.f/sqrtf(ss) : 0.f;
    } else {
        int base = (bidx-2048)*2048 + threadIdx.x*8;
        float4 z = make_float4(0.f,0.f,0.f,0.f);
        *(float4*)(r_out + base)     = z;
        *(float4*)(r_out + base + 4) = z;
    }
}

// ---------------- kernel 2b: k inverse norms + shift softmax ----------------
__global__ __launch_bounds__(256) void prep_k_kernel()
{
    int warp = threadIdx.x >> 5, lane = threadIdx.x & 31;
    int b = blockIdx.x*8 + warp;
    float4 v = *(const float4*)(g_k + (size_t)b*Mm + lane*4);
    float ss = v.x*v.x + v.y*v.y + v.z*v.z + v.w*v.w;
    #pragma unroll
    for (int o = 16; o; o >>= 1) ss += __shfl_down_sync(0xffffffffu, ss, o);
    if (lane == 0) {
        g_nk[b] = (ss > 0.f) ? 1.f/sqrtf(ss) : 0.f;
        g_sum[b] = 0.f;
        float x0 = g_slog[b*Ss+0], x1 = g_slog[b*Ss+1], x2 = g_slog[b*Ss+2];
        float mx = fmaxf(x0, fmaxf(x1, x2));
        float e0 = expf(x0-mx), e1 = expf(x1-mx), e2 = expf(x2-mx);
        float it = 1.f / (e0+e1+e2);
        g_s[b*Ss+0] = e0*it; g_s[b*Ss+1] = e1*it; g_s[b*Ss+2] = e2*it;
    }
}

// ---------------- kernel 3: sim GEMM (single-buffered, as in R9) ----------------
__global__ __launch_bounds__(256) void sim_hmma(int b_off)
{
    __shared__ __align__(16) __nv_bfloat16 As[128*PADK];
    __shared__ __align__(16) __nv_bfloat16 Bs[128*PADK];
    __shared__ float ssum[128];
    int tid = threadIdx.x, lane = tid & 31, w = tid >> 5;
    int n0 = blockIdx.x * 128, b0 = blockIdx.y * 128 + b_off;
    int wm = (w >> 1) * 32, wn = (w & 1) * 64;
    float acc[2][8][4];
    #pragma unroll
    for (int i = 0; i < 2; i++)
        #pragma unroll
        for (int j = 0; j < 8; j++)
            #pragma unroll
            for (int q = 0; q < 4; q++) acc[i][j][q] = 0.f;
    if (tid < 128) ssum[tid] = 0.f;
    int rowt = tid >> 1, kbt = (tid & 1) * 16;
    const float* ap = g_k + (size_t)(b0 + rowt)*Mm + kbt;
    const __nv_bfloat16* bp = g_mbf + (size_t)(n0 + rowt)*Mm + kbt;
    float4 ra0 = *(const float4*)(ap),   ra1 = *(const float4*)(ap+4),
           ra2 = *(const float4*)(ap+8), ra3 = *(const float4*)(ap+12);
    uint4 rb0 = *(const uint4*)(bp), rb1 = *(const uint4*)(bp+8);
    #pragma unroll
    for (int it = 0; it < 4; it++) {
        cvt_store8(&As[rowt*PADK + kbt],     ra0, ra1);
        cvt_store8(&As[rowt*PADK + kbt + 8], ra2, ra3);
        *(uint4*)(&Bs[rowt*PADK + kbt])     = rb0;
        *(uint4*)(&Bs[rowt*PADK + kbt + 8]) = rb1;
        __syncthreads();
        if (it < 3) {
            ap += 32; bp += 32;
            ra0 = *(const float4*)(ap);   ra1 = *(const float4*)(ap+4);
            ra2 = *(const float4*)(ap+8); ra3 = *(const float4*)(ap+12);
            rb0 = *(const uint4*)(bp); rb1 = *(const uint4*)(bp+8);
        }
        #pragma unroll
        for (int kk = 0; kk < 32; kk += 16) {
            unsigned af[2][4], bf[4][4];
            #pragma unroll
            for (int i = 0; i < 2; i++)
                ldsm4(af[i], &As[(wm + i*16 + (lane & 15))*PADK + kk + (lane >> 4)*8]);
            #pragma unroll
            for (int j = 0; j < 4; j++)
                ldsm4(bf[j], &Bs[(wn + j*16 + (lane & 7) + ((lane >> 4) & 1)*8)*PADK
                                  + kk + ((lane >> 3) & 1)*8]);
            #pragma unroll
            for (int i = 0; i < 2; i++)
                #pragma unroll
                for (int j = 0; j < 4; j++) {
                    mma16816(acc[i][2*j],   af[i], &bf[j][0]);
                    mma16816(acc[i][2*j+1], af[i], &bf[j][2]);
                }
        }
        __syncthreads();
    }
    int r4 = lane >> 2, c2 = (lane & 3)*2;
    #pragma unroll
    for (int i = 0; i < 2; i++) {
        #pragma unroll
        for (int rs = 0; rs < 2; rs++) {
            int bl = wm + i*16 + rs*8 + r4;
            int bg = b0 + bl;
            float be2 = g_beta[bg] * 1.44269504f * g_nk[bg];
            float rsum = 0.f;
            #pragma unroll
            for (int j8 = 0; j8 < 8; j8++) {
                int ng0 = n0 + wn + j8*8 + c2;
                float v0 = fast_exp2(be2 * acc[i][j8][rs*2]   * g_nm[ng0]);
                float v1 = fast_exp2(be2 * acc[i][j8][rs*2+1] * g_nm[ng0+1]);
                *(float2*)(g_t + (size_t)bg*Nn + ng0) = make_float2(v0, v1);
                rsum += v0 + v1;
            }
            atomicAdd(&ssum[bl], rsum);
        }
    }
    __syncthreads();
    if (tid < 128) atomicAdd(&g_sum[b0 + tid], ssum[tid]);
}

// ---------------- kernel 4: head weight updates (8 floats/thread, b-split) ----------------
__global__ __launch_bounds__(256) void heads5_kernel(
    const float* __restrict__ wr, const float* __restrict__ ww,
    float* __restrict__ wr_t, float* __restrict__ ww_t, int b_off)
{
    int b = blockIdx.y + b_off;
    int n = blockIdx.x * 2048 + threadIdx.x * 8;
    int lane = threadIdx.x & 31;
    float inv = 1.f / g_sum[b];
    float g = g_gate[b], omg = 1.f - g;
    float s0 = g_s[b*Ss+0], s1 = g_s[b*Ss+1], s2 = g_s[b*Ss+2];
    const float* gt = g_t + (size_t)b * Nn;

    const float* prev[5]; float* outp[5];
    prev[0] = ww + (size_t)b*Nn; outp[0] = ww_t + (size_t)b*Nn;
    #pragma unroll
    for (int hd = 1; hd < 5; hd++) {
        size_t off = ((size_t)(hd-1)*Bb + b) * Nn;
        prev[hd] = wr + off; outp[hd] = wr_t + off;
    }
    float4 wa = *(const float4*)(gt + n);
    float4 wb = *(const float4*)(gt + n + 4);
    float4 pa[5], pb[5];
    #pragma unroll
    for (int hd = 0; hd < 5; hd++) {
        pa[hd] = *(const float4*)(prev[hd] + n);
        pb[hd] = *(const float4*)(prev[hd] + n + 4);
    }
    float wcv[10];
    wcv[1]=wa.x*inv; wcv[2]=wa.y*inv; wcv[3]=wa.z*inv; wcv[4]=wa.w*inv;
    wcv[5]=wb.x*inv; wcv[6]=wb.y*inv; wcv[7]=wb.z*inv; wcv[8]=wb.w*inv;
    wcv[0] = __shfl_up_sync(0xffffffffu, wcv[8], 1);
    wcv[9] = __shfl_down_sync(0xffffffffu, wcv[1], 1);
    float pl[5], pr[5];
    #pragma unroll
    for (int hd = 0; hd < 5; hd++) {
        pl[hd] = __shfl_up_sync(0xffffffffu, pb[hd].w, 1);
        pr[hd] = __shfl_down_sync(0xffffffffu, pa[hd].x, 1);
    }
    if (lane == 0) {
        int nl = (n - 1 + Nn) & (Nn - 1);
        wcv[0] = gt[nl] * inv;
        #pragma unroll
        for (int hd = 0; hd < 5; hd++) pl[hd] = __ldg(prev[hd] + nl);
    }
    if (lane == 31) {
        int nr = (n + 8) & (Nn - 1);
        wcv[9] = gt[nr] * inv;
        #pragma unroll
        for (int hd = 0; hd < 5; hd++) pr[hd] = __ldg(prev[hd] + nr);
    }
    #pragma unroll
    for (int hd = 0; hd < 5; hd++) {
        float pv[10];
        pv[0]=pl[hd];
        pv[1]=pa[hd].x; pv[2]=pa[hd].y; pv[3]=pa[hd].z; pv[4]=pa[hd].w;
        pv[5]=pb[hd].x; pv[6]=pb[hd].y; pv[7]=pb[hd].z; pv[8]=pb[hd].w;
        pv[9]=pr[hd];
        float wg[10];
        #pragma unroll
        for (int q = 0; q < 10; q++) wg[q] = fmaf(g, wcv[q], omg*pv[q]);
        float4 oa, ob;
        oa.x = s0*wg[2] + s1*wg[1] + s2*wg[0];
        oa.y = s0*wg[3] + s1*wg[2] + s2*wg[1];
        oa.z = s0*wg[4] + s1*wg[3] + s2*wg[2];
        oa.w = s0*wg[5] + s1*wg[4] + s2*wg[3];
        ob.x = s0*wg[6] + s1*wg[5] + s2*wg[4];
        ob.y = s0*wg[7] + s1*wg[6] + s2*wg[5];
        ob.z = s0*wg[8] + s1*wg[7] + s2*wg[6];
        ob.w = s0*wg[9] + s1*wg[8] + s2*wg[7];
        *(float4*)(outp[hd] + n)     = oa;
        *(float4*)(outp[hd] + n + 4) = ob;
    }
}

// ---------------- kernel 5: fused erase+add GEMM + m_t epilogue ----------------
__global__ __launch_bounds__(256) void memfused_hmma(
    const float* __restrict__ ww, const float* __restrict__ m, float* __restrict__ m_t)
{
    __shared__ __align__(16) __nv_bfloat16 As[32*PAD64];
    __shared__ __align__(16) __nv_bfloat16 Be[32*PADW];
    __shared__ __align__(16) __nv_bfloat16 Ba[32*PADW];
    int tid = threadIdx.x, lane = tid & 31, w = tid >> 5;
    int n0 = blockIdx.x * 64;
    int wm = (w >> 2) * 32, wn = (w & 3) * 32;
    float ae[2][4][4], aa[2][4][4];
    #pragma unroll
    for (int i = 0; i < 2; i++)
        #pragma unroll
        for (int j = 0; j < 4; j++)
            #pragma unroll
            for (int q = 0; q < 4; q++) { ae[i][j][q] = 0.f; aa[i][j][q] = 0.f; }
    int arw = tid >> 3, acl = (tid & 7) * 8;
    int brw = tid >> 3, bcl = (tid & 7) * 16;
    for (int bc = 0; bc < Bb; bc += 32) {
        const float* apw = ww + (size_t)(bc + arw)*Nn + n0 + acl;
        float4 a0 = *(const float4*)(apw), a1 = *(const float4*)(apw+4);
        cvt_store8(&As[arw*PAD64 + acl], a0, a1);
        const float* ep = g_e + (size_t)(bc + brw)*Mm + bcl;
        float4 e0 = *(const float4*)(ep),   e1 = *(const float4*)(ep+4),
               e2 = *(const float4*)(ep+8), e3 = *(const float4*)(ep+12);
        cvt_store8(&Be[brw*PADW + bcl],     e0, e1);
        cvt_store8(&Be[brw*PADW + bcl + 8], e2, e3);
        const float* apb = g_a + (size_t)(bc + brw)*Mm + bcl;
        float4 f0 = *(const float4*)(apb),   f1 = *(const float4*)(apb+4),
               f2 = *(const float4*)(apb+8), f3 = *(const float4*)(apb+12);
        cvt_store8(&Ba[brw*PADW + bcl],     f0, f1);
        cvt_store8(&Ba[brw*PADW + bcl + 8], f2, f3);
        __syncthreads();
        #pragma unroll
        for (int kk = 0; kk < 32; kk += 16) {
            unsigned af[2][4], bfe[2][4], bfa[2][4];
            #pragma unroll
            for (int i = 0; i < 2; i++)
                ldsm4t(af[i], &As[(kk + (lane & 7) + ((lane >> 4) & 1)*8)*PAD64
                                   + wm + i*16 + ((lane >> 3) & 1)*8]);
            #pragma unroll
            for (int j = 0; j < 2; j++) {
                ldsm4t(bfe[j], &Be[(kk + (lane & 15))*PADW + wn + j*16 + (lane >> 4)*8]);
                ldsm4t(bfa[j], &Ba[(kk + (lane & 15))*PADW + wn + j*16 + (lane >> 4)*8]);
            }
            #pragma unroll
            for (int i = 0; i < 2; i++)
                #pragma unroll
                for (int j = 0; j < 2; j++) {
                    mma16816(ae[i][2*j],   af[i], &bfe[j][0]);
                    mma16816(ae[i][2*j+1], af[i], &bfe[j][2]);
                    mma16816(aa[i][2*j],   af[i], &bfa[j][0]);
                    mma16816(aa[i][2*j+1], af[i], &bfa[j][2]);
                }
        }
        __syncthreads();
    }
    int r4 = lane >> 2, c2 = (lane & 3)*2;
    #pragma unroll
    for (int i = 0; i < 2; i++) {
        #pragma unroll
        for (int j8 = 0; j8 < 4; j8++) {
            int col = wn + j8*8 + c2;
            #pragma unroll
            for (int rs = 0; rs < 2; rs++) {
                int row = n0 + wm + i*16 + rs*8 + r4;
                float me0 = ae[i][j8][rs*2], me1 = ae[i][j8][rs*2+1];
                float ma0 = aa[i][j8][rs*2], ma1 = aa[i][j8][rs*2+1];
                float2 mv = *(const float2*)(m + (size_t)row*Mm + col);
                float2 o;
                o.x = mv.x * (1.f - me0) + ma0;
                o.y = mv.y * (1.f - me1) + ma1;
                *(float2*)(m_t + (size_t)row*Mm + col) = o;
            }
        }
    }
}

// ---------------- kernel 6: r_t GEMM (bf16, split-K=16, red.v2) ----------------
__global__ __launch_bounds__(256, 2) void rt_hmma4(
    const float* __restrict__ wr, float* __restrict__ r_out)
{
    __shared__ __align__(16) __nv_bfloat16 As[2][64*PADK];
    __shared__ __align__(16) __nv_bfloat16 Bs[2][32*PADW];
    int tid = threadIdx.x, lane = tid & 31, w = tid >> 5;
    int row0 = blockIdx.x * 64;
    int kb = blockIdx.y * 1024;
    int wm = (w >> 2) * 32, wn = (w & 3) * 32;
    float acc[2][4][4];
    #pragma unroll
    for (int i = 0; i < 2; i++)
        #pragma unroll
        for (int j = 0; j < 4; j++)
            #pragma unroll
            for (int q = 0; q < 4; q++) acc[i][j][q] = 0.f;
    int arow = tid >> 2, akb = (tid & 3) * 8;
    int brow = tid >> 3, bnb = (tid & 7) * 16;
    const float* aptr = wr + (size_t)(row0 + arow)*Nn + kb + akb;
    const __nv_bfloat16* bptr = g_mbf + (size_t)(kb + brow)*Mm + bnb;
    float4 ra0 = *(const float4*)(aptr), ra1 = *(const float4*)(aptr+4);
    uint4 rb0 = *(const uint4*)(bptr), rb1 = *(const uint4*)(bptr+8);
    for (int it = 0; it < 32; it++) {
        __nv_bfloat16* Ab = As[it & 1];
        __nv_bfloat16* Bbf = Bs[it & 1];
        cvt_store8(&Ab[arow*PADK + akb], ra0, ra1);
        *(uint4*)(&Bbf[brow*PADW + bnb])     = rb0;
        *(uint4*)(&Bbf[brow*PADW + bnb + 8]) = rb1;
        if (it < 31) {
            aptr += 32; bptr += (size_t)32 * Mm;
            ra0 = *(const float4*)(aptr); ra1 = *(const float4*)(aptr+4);
            rb0 = *(const uint4*)(bptr); rb1 = *(const uint4*)(bptr+8);
        }
        __syncthreads();
        #pragma unroll
        for (int kk = 0; kk < 32; kk += 16) {
            unsigned af[2][4], bf[2][4];
            #pragma unroll
            for (int i = 0; i < 2; i++)
                ldsm4(af[i], &Ab[(wm + i*16 + (lane & 15))*PADK + kk + (lane >> 4)*8]);
            #pragma unroll
            for (int j = 0; j < 2; j++)
                ldsm4t(bf[j], &Bbf[(kk + (lane & 15))*PADW + wn + j*16 + (lane >> 4)*8]);
            #pragma unroll
            for (int i = 0; i < 2; i++)
                #pragma unroll
                for (int j = 0; j < 2; j++) {
                    mma16816(acc[i][2*j],   af[i], &bf[j][0]);
                    mma16816(acc[i][2*j+1], af[i], &bf[j][2]);
                }
        }
    }
    int r4 = lane >> 2, c2 = (lane & 3)*2;
    #pragma unroll
    for (int i = 0; i < 2; i++) {
        #pragma unroll
        for (int rs = 0; rs < 2; rs++) {
            int rb = row0 + wm + i*16 + rs*8 + r4;
            int r = rb >> 9, b = rb & (Bb - 1);
            float* dst = r_out + ((size_t)b*Rr + r)*Mm;
            #pragma unroll
            for (int j8 = 0; j8 < 4; j8++) {
                int col = wn + j8*8 + c2;
                asm volatile("red.global.add.v2.f32 [%0], {%1, %2};"
                    :: "l"(dst + col), "f"(acc[i][j8][rs*2]), "f"(acc[i][j8][rs*2+1])
                    : "memory");
            }
        }
    }
}

// ---------------- streams/events ----------------
namespace {
struct HostRes {
    cudaStream_t s1, s2;
    cudaEvent_t e0, eC, eM, eS0, eS1, eS2, e1, e2;
    HostRes() {
        cudaStreamCreateWithFlags(&s1, cudaStreamNonBlocking);
        cudaStreamCreateWithFlags(&s2, cudaStreamNonBlocking);
        cudaEventCreateWithFlags(&e0, cudaEventDisableTiming);
        cudaEventCreateWithFlags(&eC, cudaEventDisableTiming);
        cudaEventCreateWithFlags(&eM, cudaEventDisableTiming);
        cudaEventCreateWithFlags(&eS0, cudaEventDisableTiming);
        cudaEventCreateWithFlags(&eS1, cudaEventDisableTiming);
        cudaEventCreateWithFlags(&eS2, cudaEventDisableTiming);
        cudaEventCreateWithFlags(&e1, cudaEventDisableTiming);
        cudaEventCreateWithFlags(&e2, cudaEventDisableTiming);
    }
};
HostRes g_res;
}

// ---------------- launch ----------------
extern "C" void kernel_launch(void* const* d_in, const int* in_sizes, int n_in,
                              void* d_out, int out_size)
{
    const float* h_t = (const float*)d_in[0];
    const float* wr  = (const float*)d_in[1];
    const float* ww  = (const float*)d_in[2];
    const float* m   = (const float*)d_in[3];
    const float* kw  = (const float*)d_in[4];
    const float* kb  = (const float*)d_in[5];
    const float* bw  = (const float*)d_in[6];
    const float* bbv = (const float*)d_in[7];
    const float* gw  = (const float*)d_in[8];
    const float* gb  = (const float*)d_in[9];
    const float* sw  = (const float*)d_in[10];
    const float* sb  = (const float*)d_in[11];
    const float* ew  = (const float*)d_in[14];
    const float* eb  = (const float*)d_in[15];
    const float* aw  = (const float*)d_in[16];
    const float* ab  = (const float*)d_in[17];

    float* out  = (float*)d_out;
    float* r_t  = out;
    float* wr_t = out + (size_t)Bb*Rr*Mm;
    float* ww_t = wr_t + (size_t)Rr*Bb*Nn;
    float* m_t  = ww_t + (size_t)Bb*Nn;

    cudaEventRecord(g_res.e0, 0);   // root — pulls side streams into capture

    // s1: prep_m -> rt GEMM (bf16)
    cudaStreamWaitEvent(g_res.s1, g_res.e0, 0);
    prep_m_kernel<<<2176, 256, 0, g_res.s1>>>(m, r_t);
    cudaEventRecord(g_res.eM, g_res.s1);
    rt_hmma4<<<dim3(2048/64, 16), 256, 0, g_res.s1>>>(wr, r_t);

    // legacy: ctrl -> prep_k
    ctrl_kernel<<<dim3(Bb/8, 8), 256>>>(h_t, kw, kb, bw, bbv, gw, gb, sw, sb, ew, eb, aw, ab);
    cudaEventRecord(g_res.eC, 0);
    prep_k_kernel<<<Bb/8, 256>>>();

    // s2: memfused after ctrl
    cudaStreamWaitEvent(g_res.s2, g_res.eC, 0);
    memfused_hmma<<<Nn/64, 256, 0, g_res.s2>>>(ww, m, m_t);

    // legacy: sim in 4 chunks of 128 batches (needs prep_k + prep_m)
    cudaStreamWaitEvent(0, g_res.eM, 0);
    sim_hmma<<<dim3(Nn/128, 1), 256>>>(0);
    cudaEventRecord(g_res.eS0, 0);
    sim_hmma<<<dim3(Nn/128, 1), 256>>>(128);
    cudaEventRecord(g_res.eS1, 0);
    sim_hmma<<<dim3(Nn/128, 1), 256>>>(256);
    cudaEventRecord(g_res.eS2, 0);
    sim_hmma<<<dim3(Nn/128, 1), 256>>>(384);

    // s2: heads chunks 0,1 after memfused (overlap sims 1..3)
    cudaStreamWaitEvent(g_res.s2, g_res.eS0, 0);
    heads5_kernel<<<dim3(Nn/2048, 128), 256, 0, g_res.s2>>>(wr, ww, wr_t, ww_t, 0);
    cudaStreamWaitEvent(g_res.s2, g_res.eS1, 0);
    heads5_kernel<<<dim3(Nn/2048, 128), 256, 0, g_res.s2>>>(wr, ww, wr_t, ww_t, 128);
    cudaEventRecord(g_res.e2, g_res.s2);

    // s1: heads chunk 2 after rt (overlaps sim 3 / legacy tail)
    cudaStreamWaitEvent(g_res.s1, g_res.eS2, 0);
    heads5_kernel<<<dim3(Nn/2048, 128), 256, 0, g_res.s1>>>(wr, ww, wr_t, ww_t, 256);
    cudaEventRecord(g_res.e1, g_res.s1);

    // legacy: heads chunk 3
    heads5_kernel<<<dim3(Nn/2048, 128), 256>>>(wr, ww, wr_t, ww_t, 384);

    cudaStreamWaitEvent(0, g_res.e1, 0);
    cudaStreamWaitEvent(0, g_res.e2, 0);
}

// round 13
// speedup vs baseline: 1.3333x; 1.0390x over previous
#include <cuda_runtime.h>
#include <cuda_bf16.h>

#define Bb 512
#define Hh 1024
#define Nn 16384
#define Mm 128
#define Rr 4
#define Ss 3

#define PADK 40
#define PADW 136
#define PAD64 72

// ---------------- scratch ----------------
__device__ __align__(16) float g_k[Bb*Mm];
__device__ __align__(16) float g_e[Bb*Mm];
__device__ __align__(16) float g_a[Bb*Mm];
__device__ float g_beta[Bb], g_gate[Bb], g_slog[Bb*Ss], g_s[Bb*Ss];
__device__ float g_nk[Bb], g_nm[Nn], g_sum[Bb];   // INVERSE norms
__device__ __align__(16) float g_t[(size_t)Bb*Nn];
__device__ __align__(16) __nv_bfloat16 g_mbf[(size_t)Nn*Mm];  // bf16 copy of m

// ---------------- helpers ----------------
__device__ __forceinline__ void ldsm4(unsigned* r, const __nv_bfloat16* p) {
    unsigned a = (unsigned)__cvta_generic_to_shared(p);
    asm volatile("ldmatrix.sync.aligned.m8n8.x4.shared.b16 {%0,%1,%2,%3}, [%4];"
        : "=r"(r[0]), "=r"(r[1]), "=r"(r[2]), "=r"(r[3]) : "r"(a));
}
__device__ __forceinline__ void ldsm4t(unsigned* r, const __nv_bfloat16* p) {
    unsigned a = (unsigned)__cvta_generic_to_shared(p);
    asm volatile("ldmatrix.sync.aligned.m8n8.x4.trans.shared.b16 {%0,%1,%2,%3}, [%4];"
        : "=r"(r[0]), "=r"(r[1]), "=r"(r[2]), "=r"(r[3]) : "r"(a));
}
__device__ __forceinline__ void mma16816(float* c, const unsigned* a, const unsigned* b) {
    asm volatile("mma.sync.aligned.m16n8k16.row.col.f32.bf16.bf16.f32 "
        "{%0,%1,%2,%3}, {%4,%5,%6,%7}, {%8,%9}, {%0,%1,%2,%3};"
        : "+f"(c[0]), "+f"(c[1]), "+f"(c[2]), "+f"(c[3])
        : "r"(a[0]), "r"(a[1]), "r"(a[2]), "r"(a[3]), "r"(b[0]), "r"(b[1]));
}
__device__ __forceinline__ void cvt_store8(__nv_bfloat16* dst, float4 v0, float4 v1) {
    __nv_bfloat162* d = (__nv_bfloat162*)dst;
    d[0] = __float22bfloat162_rn(make_float2(v0.x, v0.y));
    d[1] = __float22bfloat162_rn(make_float2(v0.z, v0.w));
    d[2] = __float22bfloat162_rn(make_float2(v1.x, v1.y));
    d[3] = __float22bfloat162_rn(make_float2(v1.z, v1.w));
}
// exp2 on the FMA pipe — no MUFU.
__device__ __forceinline__ float fast_exp2(float x) {
    float t = x + 12582912.0f;
    int ri = __float_as_int(t) - 0x4B400000;
    float f = x - (t - 12582912.0f);
    float p = 0.0013333558f;
    p = fmaf(p, f, 0.0096181298f);
    p = fmaf(p, f, 0.0555041087f);
    p = fmaf(p, f, 0.2402265070f);
    p = fmaf(p, f, 0.6931471806f);
    p = fmaf(p, f, 1.0f);
    return __int_as_float(__float_as_int(p) + (ri << 23));
}

// ---------------- kernel 1: controller projections (8x j-parallel) ----------------
__global__ __launch_bounds__(256) void ctrl_kernel(
    const float* __restrict__ h,
    const float* __restrict__ kw, const float* __restrict__ kb,
    const float* __restrict__ bw, const float* __restrict__ bbv,
    const float* __restrict__ gw, const float* __restrict__ gb,
    const float* __restrict__ sw, const float* __restrict__ sb,
    const float* __restrict__ ew, const float* __restrict__ eb,
    const float* __restrict__ aw, const float* __restrict__ ab)
{
    __shared__ float h_s[8][Hh];
    int b0 = blockIdx.x * 8;
    for (int i = threadIdx.x; i < 8*Hh; i += 256)
        h_s[i >> 10][i & 1023] = h[(size_t)(b0 + (i >> 10))*Hh + (i & 1023)];
    __syncthreads();
    int warp = threadIdx.x >> 5, lane = threadIdx.x & 31;
    for (int j = blockIdx.y*8 + warp; j < 3*Mm + 5; j += 64) {
        const float* wrow; float bias; int act;
        if (j < Mm)        { wrow = kw + (size_t)j*Hh;        bias = kb[j];      act = 0; }
        else if (j < 2*Mm) { wrow = ew + (size_t)(j-Mm)*Hh;   bias = eb[j-Mm];   act = 0; }
        else if (j < 3*Mm) { wrow = aw + (size_t)(j-2*Mm)*Hh; bias = ab[j-2*Mm]; act = 0; }
        else if (j == 384) { wrow = bw;                       bias = bbv[0];     act = 2; }
        else if (j == 385) { wrow = gw;                       bias = gb[0];      act = 0; }
        else               { wrow = sw + (size_t)(j-386)*Hh;  bias = sb[j-386];  act = 3; }
        float acc[8];
        #pragma unroll
        for (int q = 0; q < 8; q++) acc[q] = 0.f;
        for (int k = lane; k < Hh; k += 32) {
            float wv = __ldg(wrow + k);
            #pragma unroll
            for (int q = 0; q < 8; q++) acc[q] = fmaf(wv, h_s[q][k], acc[q]);
        }
        #pragma unroll
        for (int q = 0; q < 8; q++) {
            float v = acc[q];
            #pragma unroll
            for (int o = 16; o; o >>= 1) v += __shfl_down_sync(0xffffffffu, v, o);
            if (lane == 0) {
                v += bias;
                if (act == 0) v = fminf(fmaxf(v, 0.f), 1.f);
                else if (act == 2) v = fmaxf(v, 0.f);
                int b = b0 + q;
                if (j < Mm)        g_k[b*Mm + j] = v;
                else if (j < 2*Mm) g_e[b*Mm + (j-Mm)] = v;
                else if (j < 3*Mm) g_a[b*Mm + (j-2*Mm)] = v;
                else if (j == 384) g_beta[b] = v;
                else if (j == 385) g_gate[b] = v;
                else               g_slog[b*Ss + (j-386)] = v;
            }
        }
    }
}

// ---------------- kernel 2a: m inverse norms + bf16 copy + zero r_t ----------------
__global__ __launch_bounds__(256) void prep_m_kernel(const float* __restrict__ m, float* __restrict__ r_out)
{
    int warp = threadIdx.x >> 5, lane = threadIdx.x & 31;
    int bidx = blockIdx.x;
    if (bidx < 2048) {
        int n = bidx*8 + warp;
        float4 v = *(const float4*)(m + (size_t)n*Mm + lane*4);
        __nv_bfloat162* dst = (__nv_bfloat162*)(g_mbf + (size_t)n*Mm + lane*4);
        dst[0] = __float22bfloat162_rn(make_float2(v.x, v.y));
        dst[1] = __float22bfloat162_rn(make_float2(v.z, v.w));
        float ss = v.x*v.x + v.y*v.y + v.z*v.z + v.w*v.w;
        #pragma unroll
        for (int o = 16; o; o >>= 1) ss += __shfl_down_sync(0xffffffffu, ss, o);
        if (lane == 0) g_nm[n] = (ss > 0.f) ? 1.f/sqrtf(ss) : 0.f;
    } else {
        int base = (bidx-2048)*2048 + threadIdx.x*8;
        float4 z = make_float4(0.f,0.f,0.f,0.f);
        *(float4*)(r_out + base)     = z;
        *(float4*)(r_out + base + 4) = z;
    }
}

// ---------------- kernel 2b: k inverse norms + shift softmax ----------------
__global__ __launch_bounds__(256) void prep_k_kernel()
{
    int warp = threadIdx.x >> 5, lane = threadIdx.x & 31;
    int b = blockIdx.x*8 + warp;
    float4 v = *(const float4*)(g_k + (size_t)b*Mm + lane*4);
    float ss = v.x*v.x + v.y*v.y + v.z*v.z + v.w*v.w;
    #pragma unroll
    for (int o = 16; o; o >>= 1) ss += __shfl_down_sync(0xffffffffu, ss, o);
    if (lane == 0) {
        g_nk[b] = (ss > 0.f) ? 1.f/sqrtf(ss) : 0.f;
        g_sum[b] = 0.f;
        float x0 = g_slog[b*Ss+0], x1 = g_slog[b*Ss+1], x2 = g_slog[b*Ss+2];
        float mx = fmaxf(x0, fmaxf(x1, x2));
        float e0 = expf(x0-mx), e1 = expf(x1-mx), e2 = expf(x2-mx);
        float it = 1.f / (e0+e1+e2);
        g_s[b*Ss+0] = e0*it; g_s[b*Ss+1] = e1*it; g_s[b*Ss+2] = e2*it;
    }
}

// ---------------- kernel 3: sim GEMM (single-buffered, as in R9) ----------------
__global__ __launch_bounds__(256) void sim_hmma(int b_off)
{
    __shared__ __align__(16) __nv_bfloat16 As[128*PADK];
    __shared__ __align__(16) __nv_bfloat16 Bs[128*PADK];
    __shared__ float ssum[128];
    int tid = threadIdx.x, lane = tid & 31, w = tid >> 5;
    int n0 = blockIdx.x * 128, b0 = blockIdx.y * 128 + b_off;
    int wm = (w >> 1) * 32, wn = (w & 1) * 64;
    float acc[2][8][4];
    #pragma unroll
    for (int i = 0; i < 2; i++)
        #pragma unroll
        for (int j = 0; j < 8; j++)
            #pragma unroll
            for (int q = 0; q < 4; q++) acc[i][j][q] = 0.f;
    if (tid < 128) ssum[tid] = 0.f;
    int rowt = tid >> 1, kbt = (tid & 1) * 16;
    const float* ap = g_k + (size_t)(b0 + rowt)*Mm + kbt;
    const __nv_bfloat16* bp = g_mbf + (size_t)(n0 + rowt)*Mm + kbt;
    float4 ra0 = *(const float4*)(ap),   ra1 = *(const float4*)(ap+4),
           ra2 = *(const float4*)(ap+8), ra3 = *(const float4*)(ap+12);
    uint4 rb0 = *(const uint4*)(bp), rb1 = *(const uint4*)(bp+8);
    #pragma unroll
    for (int it = 0; it < 4; it++) {
        cvt_store8(&As[rowt*PADK + kbt],     ra0, ra1);
        cvt_store8(&As[rowt*PADK + kbt + 8], ra2, ra3);
        *(uint4*)(&Bs[rowt*PADK + kbt])     = rb0;
        *(uint4*)(&Bs[rowt*PADK + kbt + 8]) = rb1;
        __syncthreads();
        if (it < 3) {
            ap += 32; bp += 32;
            ra0 = *(const float4*)(ap);   ra1 = *(const float4*)(ap+4);
            ra2 = *(const float4*)(ap+8); ra3 = *(const float4*)(ap+12);
            rb0 = *(const uint4*)(bp); rb1 = *(const uint4*)(bp+8);
        }
        #pragma unroll
        for (int kk = 0; kk < 32; kk += 16) {
            unsigned af[2][4], bf[4][4];
            #pragma unroll
            for (int i = 0; i < 2; i++)
                ldsm4(af[i], &As[(wm + i*16 + (lane & 15))*PADK + kk + (lane >> 4)*8]);
            #pragma unroll
            for (int j = 0; j < 4; j++)
                ldsm4(bf[j], &Bs[(wn + j*16 + (lane & 7) + ((lane >> 4) & 1)*8)*PADK
                                  + kk + ((lane >> 3) & 1)*8]);
            #pragma unroll
            for (int i = 0; i < 2; i++)
                #pragma unroll
                for (int j = 0; j < 4; j++) {
                    mma16816(acc[i][2*j],   af[i], &bf[j][0]);
                    mma16816(acc[i][2*j+1], af[i], &bf[j][2]);
                }
        }
        __syncthreads();
    }
    int r4 = lane >> 2, c2 = (lane & 3)*2;
    #pragma unroll
    for (int i = 0; i < 2; i++) {
        #pragma unroll
        for (int rs = 0; rs < 2; rs++) {
            int bl = wm + i*16 + rs*8 + r4;
            int bg = b0 + bl;
            float be2 = g_beta[bg] * 1.44269504f * g_nk[bg];
            float rsum = 0.f;
            #pragma unroll
            for (int j8 = 0; j8 < 8; j8++) {
                int ng0 = n0 + wn + j8*8 + c2;
                float v0 = fast_exp2(be2 * acc[i][j8][rs*2]   * g_nm[ng0]);
                float v1 = fast_exp2(be2 * acc[i][j8][rs*2+1] * g_nm[ng0+1]);
                *(float2*)(g_t + (size_t)bg*Nn + ng0) = make_float2(v0, v1);
                rsum += v0 + v1;
            }
            atomicAdd(&ssum[bl], rsum);
        }
    }
    __syncthreads();
    if (tid < 128) atomicAdd(&g_sum[b0 + tid], ssum[tid]);
}

// ---------------- kernel 4: head weight updates (8 floats/thread, b-split) ----------------
__global__ __launch_bounds__(256) void heads5_kernel(
    const float* __restrict__ wr, const float* __restrict__ ww,
    float* __restrict__ wr_t, float* __restrict__ ww_t, int b_off)
{
    int b = blockIdx.y + b_off;
    int n = blockIdx.x * 2048 + threadIdx.x * 8;
    int lane = threadIdx.x & 31;
    float inv = 1.f / g_sum[b];
    float g = g_gate[b], omg = 1.f - g;
    float s0 = g_s[b*Ss+0], s1 = g_s[b*Ss+1], s2 = g_s[b*Ss+2];
    const float* gt = g_t + (size_t)b * Nn;

    const float* prev[5]; float* outp[5];
    prev[0] = ww + (size_t)b*Nn; outp[0] = ww_t + (size_t)b*Nn;
    #pragma unroll
    for (int hd = 1; hd < 5; hd++) {
        size_t off = ((size_t)(hd-1)*Bb + b) * Nn;
        prev[hd] = wr + off; outp[hd] = wr_t + off;
    }
    float4 wa = *(const float4*)(gt + n);
    float4 wb = *(const float4*)(gt + n + 4);
    float4 pa[5], pb[5];
    #pragma unroll
    for (int hd = 0; hd < 5; hd++) {
        pa[hd] = *(const float4*)(prev[hd] + n);
        pb[hd] = *(const float4*)(prev[hd] + n + 4);
    }
    float wcv[10];
    wcv[1]=wa.x*inv; wcv[2]=wa.y*inv; wcv[3]=wa.z*inv; wcv[4]=wa.w*inv;
    wcv[5]=wb.x*inv; wcv[6]=wb.y*inv; wcv[7]=wb.z*inv; wcv[8]=wb.w*inv;
    wcv[0] = __shfl_up_sync(0xffffffffu, wcv[8], 1);
    wcv[9] = __shfl_down_sync(0xffffffffu, wcv[1], 1);
    float pl[5], pr[5];
    #pragma unroll
    for (int hd = 0; hd < 5; hd++) {
        pl[hd] = __shfl_up_sync(0xffffffffu, pb[hd].w, 1);
        pr[hd] = __shfl_down_sync(0xffffffffu, pa[hd].x, 1);
    }
    if (lane == 0) {
        int nl = (n - 1 + Nn) & (Nn - 1);
        wcv[0] = gt[nl] * inv;
        #pragma unroll
        for (int hd = 0; hd < 5; hd++) pl[hd] = __ldg(prev[hd] + nl);
    }
    if (lane == 31) {
        int nr = (n + 8) & (Nn - 1);
        wcv[9] = gt[nr] * inv;
        #pragma unroll
        for (int hd = 0; hd < 5; hd++) pr[hd] = __ldg(prev[hd] + nr);
    }
    #pragma unroll
    for (int hd = 0; hd < 5; hd++) {
        float pv[10];
        pv[0]=pl[hd];
        pv[1]=pa[hd].x; pv[2]=pa[hd].y; pv[3]=pa[hd].z; pv[4]=pa[hd].w;
        pv[5]=pb[hd].x; pv[6]=pb[hd].y; pv[7]=pb[hd].z; pv[8]=pb[hd].w;
        pv[9]=pr[hd];
        float wg[10];
        #pragma unroll
        for (int q = 0; q < 10; q++) wg[q] = fmaf(g, wcv[q], omg*pv[q]);
        float4 oa, ob;
        oa.x = s0*wg[2] + s1*wg[1] + s2*wg[0];
        oa.y = s0*wg[3] + s1*wg[2] + s2*wg[1];
        oa.z = s0*wg[4] + s1*wg[3] + s2*wg[2];
        oa.w = s0*wg[5] + s1*wg[4] + s2*wg[3];
        ob.x = s0*wg[6] + s1*wg[5] + s2*wg[4];
        ob.y = s0*wg[7] + s1*wg[6] + s2*wg[5];
        ob.z = s0*wg[8] + s1*wg[7] + s2*wg[6];
        ob.w = s0*wg[9] + s1*wg[8] + s2*wg[7];
        *(float4*)(outp[hd] + n)     = oa;
        *(float4*)(outp[hd] + n + 4) = ob;
    }
}

// ---------------- kernel 5: fused erase+add GEMM + m_t epilogue ----------------
__global__ __launch_bounds__(256) void memfused_hmma(
    const float* __restrict__ ww, const float* __restrict__ m, float* __restrict__ m_t)
{
    __shared__ __align__(16) __nv_bfloat16 As[32*PAD64];
    __shared__ __align__(16) __nv_bfloat16 Be[32*PADW];
    __shared__ __align__(16) __nv_bfloat16 Ba[32*PADW];
    int tid = threadIdx.x, lane = tid & 31, w = tid >> 5;
    int n0 = blockIdx.x * 64;
    int wm = (w >> 2) * 32, wn = (w & 3) * 32;
    float ae[2][4][4], aa[2][4][4];
    #pragma unroll
    for (int i = 0; i < 2; i++)
        #pragma unroll
        for (int j = 0; j < 4; j++)
            #pragma unroll
            for (int q = 0; q < 4; q++) { ae[i][j][q] = 0.f; aa[i][j][q] = 0.f; }
    int arw = tid >> 3, acl = (tid & 7) * 8;
    int brw = tid >> 3, bcl = (tid & 7) * 16;
    for (int bc = 0; bc < Bb; bc += 32) {
        const float* apw = ww + (size_t)(bc + arw)*Nn + n0 + acl;
        float4 a0 = *(const float4*)(apw), a1 = *(const float4*)(apw+4);
        cvt_store8(&As[arw*PAD64 + acl], a0, a1);
        const float* ep = g_e + (size_t)(bc + brw)*Mm + bcl;
        float4 e0 = *(const float4*)(ep),   e1 = *(const float4*)(ep+4),
               e2 = *(const float4*)(ep+8), e3 = *(const float4*)(ep+12);
        cvt_store8(&Be[brw*PADW + bcl],     e0, e1);
        cvt_store8(&Be[brw*PADW + bcl + 8], e2, e3);
        const float* apb = g_a + (size_t)(bc + brw)*Mm + bcl;
        float4 f0 = *(const float4*)(apb),   f1 = *(const float4*)(apb+4),
               f2 = *(const float4*)(apb+8), f3 = *(const float4*)(apb+12);
        cvt_store8(&Ba[brw*PADW + bcl],     f0, f1);
        cvt_store8(&Ba[brw*PADW + bcl + 8], f2, f3);
        __syncthreads();
        #pragma unroll
        for (int kk = 0; kk < 32; kk += 16) {
            unsigned af[2][4], bfe[2][4], bfa[2][4];
            #pragma unroll
            for (int i = 0; i < 2; i++)
                ldsm4t(af[i], &As[(kk + (lane & 7) + ((lane >> 4) & 1)*8)*PAD64
                                   + wm + i*16 + ((lane >> 3) & 1)*8]);
            #pragma unroll
            for (int j = 0; j < 2; j++) {
                ldsm4t(bfe[j], &Be[(kk + (lane & 15))*PADW + wn + j*16 + (lane >> 4)*8]);
                ldsm4t(bfa[j], &Ba[(kk + (lane & 15))*PADW + wn + j*16 + (lane >> 4)*8]);
            }
            #pragma unroll
            for (int i = 0; i < 2; i++)
                #pragma unroll
                for (int j = 0; j < 2; j++) {
                    mma16816(ae[i][2*j],   af[i], &bfe[j][0]);
                    mma16816(ae[i][2*j+1], af[i], &bfe[j][2]);
                    mma16816(aa[i][2*j],   af[i], &bfa[j][0]);
                    mma16816(aa[i][2*j+1], af[i], &bfa[j][2]);
                }
        }
        __syncthreads();
    }
    int r4 = lane >> 2, c2 = (lane & 3)*2;
    #pragma unroll
    for (int i = 0; i < 2; i++) {
        #pragma unroll
        for (int j8 = 0; j8 < 4; j8++) {
            int col = wn + j8*8 + c2;
            #pragma unroll
            for (int rs = 0; rs < 2; rs++) {
                int row = n0 + wm + i*16 + rs*8 + r4;
                float me0 = ae[i][j8][rs*2], me1 = ae[i][j8][rs*2+1];
                float ma0 = aa[i][j8][rs*2], ma1 = aa[i][j8][rs*2+1];
                float2 mv = *(const float2*)(m + (size_t)row*Mm + col);
                float2 o;
                o.x = mv.x * (1.f - me0) + ma0;
                o.y = mv.y * (1.f - me1) + ma1;
                *(float2*)(m_t + (size_t)row*Mm + col) = o;
            }
        }
    }
}

// ---------------- kernel 6: r_t GEMM (bf16, split-K=16, red.v2) ----------------
__global__ __launch_bounds__(256, 2) void rt_hmma4(
    const float* __restrict__ wr, float* __restrict__ r_out)
{
    __shared__ __align__(16) __nv_bfloat16 As[2][64*PADK];
    __shared__ __align__(16) __nv_bfloat16 Bs[2][32*PADW];
    int tid = threadIdx.x, lane = tid & 31, w = tid >> 5;
    int row0 = blockIdx.x * 64;
    int kb = blockIdx.y * 1024;
    int wm = (w >> 2) * 32, wn = (w & 3) * 32;
    float acc[2][4][4];
    #pragma unroll
    for (int i = 0; i < 2; i++)
        #pragma unroll
        for (int j = 0; j < 4; j++)
            #pragma unroll
            for (int q = 0; q < 4; q++) acc[i][j][q] = 0.f;
    int arow = tid >> 2, akb = (tid & 3) * 8;
    int brow = tid >> 3, bnb = (tid & 7) * 16;
    const float* aptr = wr + (size_t)(row0 + arow)*Nn + kb + akb;
    const __nv_bfloat16* bptr = g_mbf + (size_t)(kb + brow)*Mm + bnb;
    float4 ra0 = *(const float4*)(aptr), ra1 = *(const float4*)(aptr+4);
    uint4 rb0 = *(const uint4*)(bptr), rb1 = *(const uint4*)(bptr+8);
    for (int it = 0; it < 32; it++) {
        __nv_bfloat16* Ab = As[it & 1];
        __nv_bfloat16* Bbf = Bs[it & 1];
        cvt_store8(&Ab[arow*PADK + akb], ra0, ra1);
        *(uint4*)(&Bbf[brow*PADW + bnb])     = rb0;
        *(uint4*)(&Bbf[brow*PADW + bnb + 8]) = rb1;
        if (it < 31) {
            aptr += 32; bptr += (size_t)32 * Mm;
            ra0 = *(const float4*)(aptr); ra1 = *(const float4*)(aptr+4);
            rb0 = *(const uint4*)(bptr); rb1 = *(const uint4*)(bptr+8);
        }
        __syncthreads();
        #pragma unroll
        for (int kk = 0; kk < 32; kk += 16) {
            unsigned af[2][4], bf[2][4];
            #pragma unroll
            for (int i = 0; i < 2; i++)
                ldsm4(af[i], &Ab[(wm + i*16 + (lane & 15))*PADK + kk + (lane >> 4)*8]);
            #pragma unroll
            for (int j = 0; j < 2; j++)
                ldsm4t(bf[j], &Bbf[(kk + (lane & 15))*PADW + wn + j*16 + (lane >> 4)*8]);
            #pragma unroll
            for (int i = 0; i < 2; i++)
                #pragma unroll
                for (int j = 0; j < 2; j++) {
                    mma16816(acc[i][2*j],   af[i], &bf[j][0]);
                    mma16816(acc[i][2*j+1], af[i], &bf[j][2]);
                }
        }
    }
    int r4 = lane >> 2, c2 = (lane & 3)*2;
    #pragma unroll
    for (int i = 0; i < 2; i++) {
        #pragma unroll
        for (int rs = 0; rs < 2; rs++) {
            int rb = row0 + wm + i*16 + rs*8 + r4;
            int r = rb >> 9, b = rb & (Bb - 1);
            float* dst = r_out + ((size_t)b*Rr + r)*Mm;
            #pragma unroll
            for (int j8 = 0; j8 < 4; j8++) {
                int col = wn + j8*8 + c2;
                asm volatile("red.global.add.v2.f32 [%0], {%1, %2};"
                    :: "l"(dst + col), "f"(acc[i][j8][rs*2]), "f"(acc[i][j8][rs*2+1])
                    : "memory");
            }
        }
    }
}

// ---------------- streams/events ----------------
namespace {
struct HostRes {
    cudaStream_t s1, s2, s3;
    cudaEvent_t e0, eC, eM, eSA, eSB, e1, e2, e3;
    HostRes() {
        cudaStreamCreateWithFlags(&s1, cudaStreamNonBlocking);
        cudaStreamCreateWithFlags(&s2, cudaStreamNonBlocking);
        cudaStreamCreateWithFlags(&s3, cudaStreamNonBlocking);
        cudaEventCreateWithFlags(&e0, cudaEventDisableTiming);
        cudaEventCreateWithFlags(&eC, cudaEventDisableTiming);
        cudaEventCreateWithFlags(&eM, cudaEventDisableTiming);
        cudaEventCreateWithFlags(&eSA, cudaEventDisableTiming);
        cudaEventCreateWithFlags(&eSB, cudaEventDisableTiming);
        cudaEventCreateWithFlags(&e1, cudaEventDisableTiming);
        cudaEventCreateWithFlags(&e2, cudaEventDisableTiming);
        cudaEventCreateWithFlags(&e3, cudaEventDisableTiming);
    }
};
HostRes g_res;
}

// ---------------- launch ----------------
extern "C" void kernel_launch(void* const* d_in, const int* in_sizes, int n_in,
                              void* d_out, int out_size)
{
    const float* h_t = (const float*)d_in[0];
    const float* wr  = (const float*)d_in[1];
    const float* ww  = (const float*)d_in[2];
    const float* m   = (const float*)d_in[3];
    const float* kw  = (const float*)d_in[4];
    const float* kb  = (const float*)d_in[5];
    const float* bw  = (const float*)d_in[6];
    const float* bbv = (const float*)d_in[7];
    const float* gw  = (const float*)d_in[8];
    const float* gb  = (const float*)d_in[9];
    const float* sw  = (const float*)d_in[10];
    const float* sb  = (const float*)d_in[11];
    const float* ew  = (const float*)d_in[14];
    const float* eb  = (const float*)d_in[15];
    const float* aw  = (const float*)d_in[16];
    const float* ab  = (const float*)d_in[17];

    float* out  = (float*)d_out;
    float* r_t  = out;
    float* wr_t = out + (size_t)Bb*Rr*Mm;
    float* ww_t = wr_t + (size_t)Rr*Bb*Nn;
    float* m_t  = ww_t + (size_t)Bb*Nn;

    cudaEventRecord(g_res.e0, 0);   // root — pulls side streams into capture

    // s1: prep_m -> rt GEMM (bf16)
    cudaStreamWaitEvent(g_res.s1, g_res.e0, 0);
    prep_m_kernel<<<2176, 256, 0, g_res.s1>>>(m, r_t);
    cudaEventRecord(g_res.eM, g_res.s1);
    rt_hmma4<<<dim3(2048/64, 16), 256, 0, g_res.s1>>>(wr, r_t);
    cudaEventRecord(g_res.e1, g_res.s1);

    // legacy: ctrl -> prep_k
    ctrl_kernel<<<dim3(Bb/8, 8), 256>>>(h_t, kw, kb, bw, bbv, gw, gb, sw, sb, ew, eb, aw, ab);
    cudaEventRecord(g_res.eC, 0);
    prep_k_kernel<<<Bb/8, 256>>>();

    // s2: memfused after ctrl
    cudaStreamWaitEvent(g_res.s2, g_res.eC, 0);
    memfused_hmma<<<Nn/64, 256, 0, g_res.s2>>>(ww, m, m_t);

    // legacy: sim halves (chip-filling grids), needs prep_k + prep_m
    cudaStreamWaitEvent(0, g_res.eM, 0);
    sim_hmma<<<dim3(Nn/128, 2), 256>>>(0);          // b 0..255
    cudaEventRecord(g_res.eSA, 0);
    sim_hmma<<<dim3(Nn/128, 2), 256>>>(256);        // b 256..511
    cudaEventRecord(g_res.eSB, 0);

    // s2: heads b 0..127 after simA (memfused already queued ahead on s2)
    cudaStreamWaitEvent(g_res.s2, g_res.eSA, 0);
    heads5_kernel<<<dim3(Nn/2048, 128), 256, 0, g_res.s2>>>(wr, ww, wr_t, ww_t, 0);
    // s3: heads b 128..255 after simA (independent of rt!)
    cudaStreamWaitEvent(g_res.s3, g_res.eSA, 0);
    heads5_kernel<<<dim3(Nn/2048, 128), 256, 0, g_res.s3>>>(wr, ww, wr_t, ww_t, 128);
    cudaEventRecord(g_res.e3, g_res.s3);

    // tail: after simB, split remaining 256 batches across legacy + s2
    heads5_kernel<<<dim3(Nn/2048, 128), 256>>>(wr, ww, wr_t, ww_t, 256);        // legacy
    cudaStreamWaitEvent(g_res.s2, g_res.eSB, 0);
    heads5_kernel<<<dim3(Nn/2048, 128), 256, 0, g_res.s2>>>(wr, ww, wr_t, ww_t, 384);
    cudaEventRecord(g_res.e2, g_res.s2);

    cudaStreamWaitEvent(0, g_res.e1, 0);
    cudaStreamWaitEvent(0, g_res.e2, 0);
    cudaStreamWaitEvent(0, g_res.e3, 0);
}

// round 15
// speedup vs baseline: 1.3345x; 1.0009x over previous
#include <cuda_runtime.h>
#include <cuda_bf16.h>

#define Bb 512
#define Hh 1024
#define Nn 16384
#define Mm 128
#define Rr 4
#define Ss 3

#define PADK 40
#define PADW 136
#define PAD64 72

// ---------------- scratch ----------------
__device__ __align__(16) float g_k[Bb*Mm];
__device__ __align__(16) float g_e[Bb*Mm];
__device__ __align__(16) float g_a[Bb*Mm];
__device__ float g_beta[Bb], g_gate[Bb], g_slog[Bb*Ss], g_s[Bb*Ss];
__device__ float g_nk[Bb], g_nm[Nn], g_sum[Bb];   // INVERSE norms
__device__ __align__(16) __nv_bfloat16 g_t[(size_t)Bb*Nn];    // bf16 now
__device__ __align__(16) __nv_bfloat16 g_mbf[(size_t)Nn*Mm];  // bf16 copy of m

// ---------------- helpers ----------------
__device__ __forceinline__ void ldsm4(unsigned* r, const __nv_bfloat16* p) {
    unsigned a = (unsigned)__cvta_generic_to_shared(p);
    asm volatile("ldmatrix.sync.aligned.m8n8.x4.shared.b16 {%0,%1,%2,%3}, [%4];"
        : "=r"(r[0]), "=r"(r[1]), "=r"(r[2]), "=r"(r[3]) : "r"(a));
}
__device__ __forceinline__ void ldsm4t(unsigned* r, const __nv_bfloat16* p) {
    unsigned a = (unsigned)__cvta_generic_to_shared(p);
    asm volatile("ldmatrix.sync.aligned.m8n8.x4.trans.shared.b16 {%0,%1,%2,%3}, [%4];"
        : "=r"(r[0]), "=r"(r[1]), "=r"(r[2]), "=r"(r[3]) : "r"(a));
}
__device__ __forceinline__ void mma16816(float* c, const unsigned* a, const unsigned* b) {
    asm volatile("mma.sync.aligned.m16n8k16.row.col.f32.bf16.bf16.f32 "
        "{%0,%1,%2,%3}, {%4,%5,%6,%7}, {%8,%9}, {%0,%1,%2,%3};"
        : "+f"(c[0]), "+f"(c[1]), "+f"(c[2]), "+f"(c[3])
        : "r"(a[0]), "r"(a[1]), "r"(a[2]), "r"(a[3]), "r"(b[0]), "r"(b[1]));
}
__device__ __forceinline__ void cvt_store8(__nv_bfloat16* dst, float4 v0, float4 v1) {
    __nv_bfloat162* d = (__nv_bfloat162*)dst;
    d[0] = __float22bfloat162_rn(make_float2(v0.x, v0.y));
    d[1] = __float22bfloat162_rn(make_float2(v0.z, v0.w));
    d[2] = __float22bfloat162_rn(make_float2(v1.x, v1.y));
    d[3] = __float22bfloat162_rn(make_float2(v1.z, v1.w));
}
// exp2 on the FMA pipe — no MUFU.
__device__ __forceinline__ float fast_exp2(float x) {
    float t = x + 12582912.0f;
    int ri = __float_as_int(t) - 0x4B400000;
    float f = x - (t - 12582912.0f);
    float p = 0.0013333558f;
    p = fmaf(p, f, 0.0096181298f);
    p = fmaf(p, f, 0.0555041087f);
    p = fmaf(p, f, 0.2402265070f);
    p = fmaf(p, f, 0.6931471806f);
    p = fmaf(p, f, 1.0f);
    return __int_as_float(__float_as_int(p) + (ri << 23));
}

// ---------------- kernel 1: controller projections (8x j-parallel) ----------------
__global__ __launch_bounds__(256) void ctrl_kernel(
    const float* __restrict__ h,
    const float* __restrict__ kw, const float* __restrict__ kb,
    const float* __restrict__ bw, const float* __restrict__ bbv,
    const float* __restrict__ gw, const float* __restrict__ gb,
    const float* __restrict__ sw, const float* __restrict__ sb,
    const float* __restrict__ ew, const float* __restrict__ eb,
    const float* __restrict__ aw, const float* __restrict__ ab)
{
    __shared__ float h_s[8][Hh];
    int b0 = blockIdx.x * 8;
    for (int i = threadIdx.x; i < 8*Hh; i += 256)
        h_s[i >> 10][i & 1023] = h[(size_t)(b0 + (i >> 10))*Hh + (i & 1023)];
    __syncthreads();
    int warp = threadIdx.x >> 5, lane = threadIdx.x & 31;
    for (int j = blockIdx.y*8 + warp; j < 3*Mm + 5; j += 64) {
        const float* wrow; float bias; int act;
        if (j < Mm)        { wrow = kw + (size_t)j*Hh;        bias = kb[j];      act = 0; }
        else if (j < 2*Mm) { wrow = ew + (size_t)(j-Mm)*Hh;   bias = eb[j-Mm];   act = 0; }
        else if (j < 3*Mm) { wrow = aw + (size_t)(j-2*Mm)*Hh; bias = ab[j-2*Mm]; act = 0; }
        else if (j == 384) { wrow = bw;                       bias = bbv[0];     act = 2; }
        else if (j == 385) { wrow = gw;                       bias = gb[0];      act = 0; }
        else               { wrow = sw + (size_t)(j-386)*Hh;  bias = sb[j-386];  act = 3; }
        float acc[8];
        #pragma unroll
        for (int q = 0; q < 8; q++) acc[q] = 0.f;
        for (int k = lane; k < Hh; k += 32) {
            float wv = __ldg(wrow + k);
            #pragma unroll
            for (int q = 0; q < 8; q++) acc[q] = fmaf(wv, h_s[q][k], acc[q]);
        }
        #pragma unroll
        for (int q = 0; q < 8; q++) {
            float v = acc[q];
            #pragma unroll
            for (int o = 16; o; o >>= 1) v += __shfl_down_sync(0xffffffffu, v, o);
            if (lane == 0) {
                v += bias;
                if (act == 0) v = fminf(fmaxf(v, 0.f), 1.f);
                else if (act == 2) v = fmaxf(v, 0.f);
                int b = b0 + q;
                if (j < Mm)        g_k[b*Mm + j] = v;
                else if (j < 2*Mm) g_e[b*Mm + (j-Mm)] = v;
                else if (j < 3*Mm) g_a[b*Mm + (j-2*Mm)] = v;
                else if (j == 384) g_beta[b] = v;
                else if (j == 385) g_gate[b] = v;
                else               g_slog[b*Ss + (j-386)] = v;
            }
        }
    }
}

// ---------------- kernel 2a: m inverse norms + bf16 copy + zero r_t ----------------
__global__ __launch_bounds__(256) void prep_m_kernel(const float* __restrict__ m, float* __restrict__ r_out)
{
    int warp = threadIdx.x >> 5, lane = threadIdx.x & 31;
    int bidx = blockIdx.x;
    if (bidx < 2048) {
        int n = bidx*8 + warp;
        float4 v = *(const float4*)(m + (size_t)n*Mm + lane*4);
        __nv_bfloat162* dst = (__nv_bfloat162*)(g_mbf + (size_t)n*Mm + lane*4);
        dst[0] = __float22bfloat162_rn(make_float2(v.x, v.y));
        dst[1] = __float22bfloat162_rn(make_float2(v.z, v.w));
        float ss = v.x*v.x + v.y*v.y + v.z*v.z + v.w*v.w;
        #pragma unroll
        for (int o = 16; o; o >>= 1) ss += __shfl_down_sync(0xffffffffu, ss, o);
        if (lane == 0) g_nm[n] = (ss > 0.f) ? 1.f/sqrtf(ss) : 0.f;
    } else {
        int base = (bidx-2048)*2048 + threadIdx.x*8;
        float4 z = make_float4(0.f,0.f,0.f,0.f);
        *(float4*)(r_out + base)     = z;
        *(float4*)(r_out + base + 4) = z;
    }
}

// ---------------- kernel 2b: k inverse norms + shift softmax ----------------
__global__ __launch_bounds__(256) void prep_k_kernel()
{
    int warp = threadIdx.x >> 5, lane = threadIdx.x & 31;
    int b = blockIdx.x*8 + warp;
    float4 v = *(const float4*)(g_k + (size_t)b*Mm + lane*4);
    float ss = v.x*v.x + v.y*v.y + v.z*v.z + v.w*v.w;
    #pragma unroll
    for (int o = 16; o; o >>= 1) ss += __shfl_down_sync(0xffffffffu, ss, o);
    if (lane == 0) {
        g_nk[b] = (ss > 0.f) ? 1.f/sqrtf(ss) : 0.f;
        g_sum[b] = 0.f;
        float x0 = g_slog[b*Ss+0], x1 = g_slog[b*Ss+1], x2 = g_slog[b*Ss+2];
        float mx = fmaxf(x0, fmaxf(x1, x2));
        float e0 = expf(x0-mx), e1 = expf(x1-mx), e2 = expf(x2-mx);
        float it = 1.f / (e0+e1+e2);
        g_s[b*Ss+0] = e0*it; g_s[b*Ss+1] = e1*it; g_s[b*Ss+2] = e2*it;
    }
}

// ---------------- kernel 3: sim GEMM + poly-exp2 + row sums (bf16 g_t out) ----------------
__global__ __launch_bounds__(256) void sim_hmma(int b_off)
{
    __shared__ __align__(16) __nv_bfloat16 As[128*PADK];
    __shared__ __align__(16) __nv_bfloat16 Bs[128*PADK];
    __shared__ float ssum[128];
    int tid = threadIdx.x, lane = tid & 31, w = tid >> 5;
    int n0 = blockIdx.x * 128, b0 = blockIdx.y * 128 + b_off;
    int wm = (w >> 1) * 32, wn = (w & 1) * 64;
    float acc[2][8][4];
    #pragma unroll
    for (int i = 0; i < 2; i++)
        #pragma unroll
        for (int j = 0; j < 8; j++)
            #pragma unroll
            for (int q = 0; q < 4; q++) acc[i][j][q] = 0.f;
    if (tid < 128) ssum[tid] = 0.f;
    int rowt = tid >> 1, kbt = (tid & 1) * 16;
    const float* ap = g_k + (size_t)(b0 + rowt)*Mm + kbt;
    const __nv_bfloat16* bp = g_mbf + (size_t)(n0 + rowt)*Mm + kbt;
    float4 ra0 = *(const float4*)(ap),   ra1 = *(const float4*)(ap+4),
           ra2 = *(const float4*)(ap+8), ra3 = *(const float4*)(ap+12);
    uint4 rb0 = *(const uint4*)(bp), rb1 = *(const uint4*)(bp+8);
    #pragma unroll
    for (int it = 0; it < 4; it++) {
        cvt_store8(&As[rowt*PADK + kbt],     ra0, ra1);
        cvt_store8(&As[rowt*PADK + kbt + 8], ra2, ra3);
        *(uint4*)(&Bs[rowt*PADK + kbt])     = rb0;
        *(uint4*)(&Bs[rowt*PADK + kbt + 8]) = rb1;
        __syncthreads();
        if (it < 3) {
            ap += 32; bp += 32;
            ra0 = *(const float4*)(ap);   ra1 = *(const float4*)(ap+4);
            ra2 = *(const float4*)(ap+8); ra3 = *(const float4*)(ap+12);
            rb0 = *(const uint4*)(bp); rb1 = *(const uint4*)(bp+8);
        }
        #pragma unroll
        for (int kk = 0; kk < 32; kk += 16) {
            unsigned af[2][4], bf[4][4];
            #pragma unroll
            for (int i = 0; i < 2; i++)
                ldsm4(af[i], &As[(wm + i*16 + (lane & 15))*PADK + kk + (lane >> 4)*8]);
            #pragma unroll
            for (int j = 0; j < 4; j++)
                ldsm4(bf[j], &Bs[(wn + j*16 + (lane & 7) + ((lane >> 4) & 1)*8)*PADK
                                  + kk + ((lane >> 3) & 1)*8]);
            #pragma unroll
            for (int i = 0; i < 2; i++)
                #pragma unroll
                for (int j = 0; j < 4; j++) {
                    mma16816(acc[i][2*j],   af[i], &bf[j][0]);
                    mma16816(acc[i][2*j+1], af[i], &bf[j][2]);
                }
        }
        __syncthreads();
    }
    int r4 = lane >> 2, c2 = (lane & 3)*2;
    #pragma unroll
    for (int i = 0; i < 2; i++) {
        #pragma unroll
        for (int rs = 0; rs < 2; rs++) {
            int bl = wm + i*16 + rs*8 + r4;
            int bg = b0 + bl;
            float be2 = g_beta[bg] * 1.44269504f * g_nk[bg];
            float rsum = 0.f;
            #pragma unroll
            for (int j8 = 0; j8 < 8; j8++) {
                int ng0 = n0 + wn + j8*8 + c2;
                float v0 = fast_exp2(be2 * acc[i][j8][rs*2]   * g_nm[ng0]);
                float v1 = fast_exp2(be2 * acc[i][j8][rs*2+1] * g_nm[ng0+1]);
                *(__nv_bfloat162*)(g_t + (size_t)bg*Nn + ng0) =
                    __float22bfloat162_rn(make_float2(v0, v1));
                rsum += v0 + v1;
            }
            atomicAdd(&ssum[bl], rsum);
        }
    }
    __syncthreads();
    if (tid < 128) atomicAdd(&g_sum[b0 + tid], ssum[tid]);
}

// ---------------- kernel 4: head weight updates (bf16 g_t in) ----------------
__global__ __launch_bounds__(256) void heads5_kernel(
    const float* __restrict__ wr, const float* __restrict__ ww,
    float* __restrict__ wr_t, float* __restrict__ ww_t, int b_off)
{
    int b = blockIdx.y + b_off;
    int n = blockIdx.x * 2048 + threadIdx.x * 8;
    int lane = threadIdx.x & 31;
    float inv = 1.f / g_sum[b];
    float g = g_gate[b], omg = 1.f - g;
    float s0 = g_s[b*Ss+0], s1 = g_s[b*Ss+1], s2 = g_s[b*Ss+2];
    const __nv_bfloat16* gt = g_t + (size_t)b * Nn;

    const float* prev[5]; float* outp[5];
    prev[0] = ww + (size_t)b*Nn; outp[0] = ww_t + (size_t)b*Nn;
    #pragma unroll
    for (int hd = 1; hd < 5; hd++) {
        size_t off = ((size_t)(hd-1)*Bb + b) * Nn;
        prev[hd] = wr + off; outp[hd] = wr_t + off;
    }
    // 8 bf16 content weights in one 16B load
    uint4 wraw = *(const uint4*)(gt + n);
    float4 pa[5], pb[5];
    #pragma unroll
    for (int hd = 0; hd < 5; hd++) {
        pa[hd] = *(const float4*)(prev[hd] + n);
        pb[hd] = *(const float4*)(prev[hd] + n + 4);
    }
    float wcv[10];
    {
        float2 q0 = __bfloat1622float2(*(__nv_bfloat162*)&wraw.x);
        float2 q1 = __bfloat1622float2(*(__nv_bfloat162*)&wraw.y);
        float2 q2 = __bfloat1622float2(*(__nv_bfloat162*)&wraw.z);
        float2 q3 = __bfloat1622float2(*(__nv_bfloat162*)&wraw.w);
        wcv[1]=q0.x*inv; wcv[2]=q0.y*inv; wcv[3]=q1.x*inv; wcv[4]=q1.y*inv;
        wcv[5]=q2.x*inv; wcv[6]=q2.y*inv; wcv[7]=q3.x*inv; wcv[8]=q3.y*inv;
    }
    wcv[0] = __shfl_up_sync(0xffffffffu, wcv[8], 1);
    wcv[9] = __shfl_down_sync(0xffffffffu, wcv[1], 1);
    float pl[5], pr[5];
    #pragma unroll
    for (int hd = 0; hd < 5; hd++) {
        pl[hd] = __shfl_up_sync(0xffffffffu, pb[hd].w, 1);
        pr[hd] = __shfl_down_sync(0xffffffffu, pa[hd].x, 1);
    }
    if (lane == 0) {
        int nl = (n - 1 + Nn) & (Nn - 1);
        wcv[0] = __bfloat162float(gt[nl]) * inv;
        #pragma unroll
        for (int hd = 0; hd < 5; hd++) pl[hd] = __ldg(prev[hd] + nl);
    }
    if (lane == 31) {
        int nr = (n + 8) & (Nn - 1);
        wcv[9] = __bfloat162float(gt[nr]) * inv;
        #pragma unroll
        for (int hd = 0; hd < 5; hd++) pr[hd] = __ldg(prev[hd] + nr);
    }
    #pragma unroll
    for (int hd = 0; hd < 5; hd++) {
        float pv[10];
        pv[0]=pl[hd];
        pv[1]=pa[hd].x; pv[2]=pa[hd].y; pv[3]=pa[hd].z; pv[4]=pa[hd].w;
        pv[5]=pb[hd].x; pv[6]=pb[hd].y; pv[7]=pb[hd].z; pv[8]=pb[hd].w;
        pv[9]=pr[hd];
        float wg[10];
        #pragma unroll
        for (int q = 0; q < 10; q++) wg[q] = fmaf(g, wcv[q], omg*pv[q]);
        float4 oa, ob;
        oa.x = s0*wg[2] + s1*wg[1] + s2*wg[0];
        oa.y = s0*wg[3] + s1*wg[2] + s2*wg[1];
        oa.z = s0*wg[4] + s1*wg[3] + s2*wg[2];
        oa.w = s0*wg[5] + s1*wg[4] + s2*wg[3];
        ob.x = s0*wg[6] + s1*wg[5] + s2*wg[4];
        ob.y = s0*wg[7] + s1*wg[6] + s2*wg[5];
        ob.z = s0*wg[8] + s1*wg[7] + s2*wg[6];
        ob.w = s0*wg[9] + s1*wg[8] + s2*wg[7];
        *(float4*)(outp[hd] + n)     = oa;
        *(float4*)(outp[hd] + n + 4) = ob;
    }
}

// ---------------- kernel 5: fused erase+add GEMM + m_t epilogue ----------------
__global__ __launch_bounds__(256) void memfused_hmma(
    const float* __restrict__ ww, const float* __restrict__ m, float* __restrict__ m_t)
{
    __shared__ __align__(16) __nv_bfloat16 As[32*PAD64];
    __shared__ __align__(16) __nv_bfloat16 Be[32*PADW];
    __shared__ __align__(16) __nv_bfloat16 Ba[32*PADW];
    int tid = threadIdx.x, lane = tid & 31, w = tid >> 5;
    int n0 = blockIdx.x * 64;
    int wm = (w >> 2) * 32, wn = (w & 3) * 32;
    float ae[2][4][4], aa[2][4][4];
    #pragma unroll
    for (int i = 0; i < 2; i++)
        #pragma unroll
        for (int j = 0; j < 4; j++)
            #pragma unroll
            for (int q = 0; q < 4; q++) { ae[i][j][q] = 0.f; aa[i][j][q] = 0.f; }
    int arw = tid >> 3, acl = (tid & 7) * 8;
    int brw = tid >> 3, bcl = (tid & 7) * 16;
    for (int bc = 0; bc < Bb; bc += 32) {
        const float* apw = ww + (size_t)(bc + arw)*Nn + n0 + acl;
        float4 a0 = *(const float4*)(apw), a1 = *(const float4*)(apw+4);
        cvt_store8(&As[arw*PAD64 + acl], a0, a1);
        const float* ep = g_e + (size_t)(bc + brw)*Mm + bcl;
        float4 e0 = *(const float4*)(ep),   e1 = *(const float4*)(ep+4),
               e2 = *(const float4*)(ep+8), e3 = *(const float4*)(ep+12);
        cvt_store8(&Be[brw*PADW + bcl],     e0, e1);
        cvt_store8(&Be[brw*PADW + bcl + 8], e2, e3);
        const float* apb = g_a + (size_t)(bc + brw)*Mm + bcl;
        float4 f0 = *(const float4*)(apb),   f1 = *(const float4*)(apb+4),
               f2 = *(const float4*)(apb+8), f3 = *(const float4*)(apb+12);
        cvt_store8(&Ba[brw*PADW + bcl],     f0, f1);
        cvt_store8(&Ba[brw*PADW + bcl + 8], f2, f3);
        __syncthreads();
        #pragma unroll
        for (int kk = 0; kk < 32; kk += 16) {
            unsigned af[2][4], bfe[2][4], bfa[2][4];
            #pragma unroll
            for (int i = 0; i < 2; i++)
                ldsm4t(af[i], &As[(kk + (lane & 7) + ((lane >> 4) & 1)*8)*PAD64
                                   + wm + i*16 + ((lane >> 3) & 1)*8]);
            #pragma unroll
            for (int j = 0; j < 2; j++) {
                ldsm4t(bfe[j], &Be[(kk + (lane & 15))*PADW + wn + j*16 + (lane >> 4)*8]);
                ldsm4t(bfa[j], &Ba[(kk + (lane & 15))*PADW + wn + j*16 + (lane >> 4)*8]);
            }
            #pragma unroll
            for (int i = 0; i < 2; i++)
                #pragma unroll
                for (int j = 0; j < 2; j++) {
                    mma16816(ae[i][2*j],   af[i], &bfe[j][0]);
                    mma16816(ae[i][2*j+1], af[i], &bfe[j][2]);
                    mma16816(aa[i][2*j],   af[i], &bfa[j][0]);
                    mma16816(aa[i][2*j+1], af[i], &bfa[j][2]);
                }
        }
        __syncthreads();
    }
    int r4 = lane >> 2, c2 = (lane & 3)*2;
    #pragma unroll
    for (int i = 0; i < 2; i++) {
        #pragma unroll
        for (int j8 = 0; j8 < 4; j8++) {
            int col = wn + j8*8 + c2;
            #pragma unroll
            for (int rs = 0; rs < 2; rs++) {
                int row = n0 + wm + i*16 + rs*8 + r4;
                float me0 = ae[i][j8][rs*2], me1 = ae[i][j8][rs*2+1];
                float ma0 = aa[i][j8][rs*2], ma1 = aa[i][j8][rs*2+1];
                float2 mv = *(const float2*)(m + (size_t)row*Mm + col);
                float2 o;
                o.x = mv.x * (1.f - me0) + ma0;
                o.y = mv.y * (1.f - me1) + ma1;
                *(float2*)(m_t + (size_t)row*Mm + col) = o;
            }
        }
    }
}

// ---------------- kernel 6: r_t GEMM (bf16, split-K=16, red.v2) ----------------
__global__ __launch_bounds__(256, 2) void rt_hmma4(
    const float* __restrict__ wr, float* __restrict__ r_out)
{
    __shared__ __align__(16) __nv_bfloat16 As[2][64*PADK];
    __shared__ __align__(16) __nv_bfloat16 Bs[2][32*PADW];
    int tid = threadIdx.x, lane = tid & 31, w = tid >> 5;
    int row0 = blockIdx.x * 64;
    int kb = blockIdx.y * 1024;
    int wm = (w >> 2) * 32, wn = (w & 3) * 32;
    float acc[2][4][4];
    #pragma unroll
    for (int i = 0; i < 2; i++)
        #pragma unroll
        for (int j = 0; j < 4; j++)
            #pragma unroll
            for (int q = 0; q < 4; q++) acc[i][j][q] = 0.f;
    int arow = tid >> 2, akb = (tid & 3) * 8;
    int brow = tid >> 3, bnb = (tid & 7) * 16;
    const float* aptr = wr + (size_t)(row0 + arow)*Nn + kb + akb;
    const __nv_bfloat16* bptr = g_mbf + (size_t)(kb + brow)*Mm + bnb;
    float4 ra0 = *(const float4*)(aptr), ra1 = *(const float4*)(aptr+4);
    uint4 rb0 = *(const uint4*)(bptr), rb1 = *(const uint4*)(bptr+8);
    for (int it = 0; it < 32; it++) {
        __nv_bfloat16* Ab = As[it & 1];
        __nv_bfloat16* Bbf = Bs[it & 1];
        cvt_store8(&Ab[arow*PADK + akb], ra0, ra1);
        *(uint4*)(&Bbf[brow*PADW + bnb])     = rb0;
        *(uint4*)(&Bbf[brow*PADW + bnb + 8]) = rb1;
        if (it < 31) {
            aptr += 32; bptr += (size_t)32 * Mm;
            ra0 = *(const float4*)(aptr); ra1 = *(const float4*)(aptr+4);
            rb0 = *(const uint4*)(bptr); rb1 = *(const uint4*)(bptr+8);
        }
        __syncthreads();
        #pragma unroll
        for (int kk = 0; kk < 32; kk += 16) {
            unsigned af[2][4], bf[2][4];
            #pragma unroll
            for (int i = 0; i < 2; i++)
                ldsm4(af[i], &Ab[(wm + i*16 + (lane & 15))*PADK + kk + (lane >> 4)*8]);
            #pragma unroll
            for (int j = 0; j < 2; j++)
                ldsm4t(bf[j], &Bbf[(kk + (lane & 15))*PADW + wn + j*16 + (lane >> 4)*8]);
            #pragma unroll
            for (int i = 0; i < 2; i++)
                #pragma unroll
                for (int j = 0; j < 2; j++) {
                    mma16816(acc[i][2*j],   af[i], &bf[j][0]);
                    mma16816(acc[i][2*j+1], af[i], &bf[j][2]);
                }
        }
    }
    int r4 = lane >> 2, c2 = (lane & 3)*2;
    #pragma unroll
    for (int i = 0; i < 2; i++) {
        #pragma unroll
        for (int rs = 0; rs < 2; rs++) {
            int rb = row0 + wm + i*16 + rs*8 + r4;
            int r = rb >> 9, b = rb & (Bb - 1);
            float* dst = r_out + ((size_t)b*Rr + r)*Mm;
            #pragma unroll
            for (int j8 = 0; j8 < 4; j8++) {
                int col = wn + j8*8 + c2;
                asm volatile("red.global.add.v2.f32 [%0], {%1, %2};"
                    :: "l"(dst + col), "f"(acc[i][j8][rs*2]), "f"(acc[i][j8][rs*2+1])
                    : "memory");
            }
        }
    }
}

// ---------------- streams/events ----------------
namespace {
struct HostRes {
    cudaStream_t s1, s2, s3;
    cudaEvent_t e0, eC, eM, eSA, eSB, e1, e2, e3;
    HostRes() {
        cudaStreamCreateWithFlags(&s1, cudaStreamNonBlocking);
        cudaStreamCreateWithFlags(&s2, cudaStreamNonBlocking);
        cudaStreamCreateWithFlags(&s3, cudaStreamNonBlocking);
        cudaEventCreateWithFlags(&e0, cudaEventDisableTiming);
        cudaEventCreateWithFlags(&eC, cudaEventDisableTiming);
        cudaEventCreateWithFlags(&eM, cudaEventDisableTiming);
        cudaEventCreateWithFlags(&eSA, cudaEventDisableTiming);
        cudaEventCreateWithFlags(&eSB, cudaEventDisableTiming);
        cudaEventCreateWithFlags(&e1, cudaEventDisableTiming);
        cudaEventCreateWithFlags(&e2, cudaEventDisableTiming);
        cudaEventCreateWithFlags(&e3, cudaEventDisableTiming);
    }
};
HostRes g_res;
}

// ---------------- launch ----------------
extern "C" void kernel_launch(void* const* d_in, const int* in_sizes, int n_in,
                              void* d_out, int out_size)
{
    const float* h_t = (const float*)d_in[0];
    const float* wr  = (const float*)d_in[1];
    const float* ww  = (const float*)d_in[2];
    const float* m   = (const float*)d_in[3];
    const float* kw  = (const float*)d_in[4];
    const float* kb  = (const float*)d_in[5];
    const float* bw  = (const float*)d_in[6];
    const float* bbv = (const float*)d_in[7];
    const float* gw  = (const float*)d_in[8];
    const float* gb  = (const float*)d_in[9];
    const float* sw  = (const float*)d_in[10];
    const float* sb  = (const float*)d_in[11];
    const float* ew  = (const float*)d_in[14];
    const float* eb  = (const float*)d_in[15];
    const float* aw  = (const float*)d_in[16];
    const float* ab  = (const float*)d_in[17];

    float* out  = (float*)d_out;
    float* r_t  = out;
    float* wr_t = out + (size_t)Bb*Rr*Mm;
    float* ww_t = wr_t + (size_t)Rr*Bb*Nn;
    float* m_t  = ww_t + (size_t)Bb*Nn;

    cudaEventRecord(g_res.e0, 0);   // root — pulls side streams into capture

    // s1: prep_m -> rt GEMM (bf16)
    cudaStreamWaitEvent(g_res.s1, g_res.e0, 0);
    prep_m_kernel<<<2176, 256, 0, g_res.s1>>>(m, r_t);
    cudaEventRecord(g_res.eM, g_res.s1);
    rt_hmma4<<<dim3(2048/64, 16), 256, 0, g_res.s1>>>(wr, r_t);
    cudaEventRecord(g_res.e1, g_res.s1);

    // legacy: ctrl -> prep_k
    ctrl_kernel<<<dim3(Bb/8, 8), 256>>>(h_t, kw, kb, bw, bbv, gw, gb, sw, sb, ew, eb, aw, ab);
    cudaEventRecord(g_res.eC, 0);
    prep_k_kernel<<<Bb/8, 256>>>();

    // s2: memfused after ctrl
    cudaStreamWaitEvent(g_res.s2, g_res.eC, 0);
    memfused_hmma<<<Nn/64, 256, 0, g_res.s2>>>(ww, m, m_t);

    // legacy: sim halves (chip-filling grids), needs prep_k + prep_m
    cudaStreamWaitEvent(0, g_res.eM, 0);
    sim_hmma<<<dim3(Nn/128, 2), 256>>>(0);          // b 0..255
    cudaEventRecord(g_res.eSA, 0);
    sim_hmma<<<dim3(Nn/128, 2), 256>>>(256);        // b 256..511
    cudaEventRecord(g_res.eSB, 0);

    // s2: heads b 0..127 after simA (memfused already queued ahead on s2)
    cudaStreamWaitEvent(g_res.s2, g_res.eSA, 0);
    heads5_kernel<<<dim3(Nn/2048, 128), 256, 0, g_res.s2>>>(wr, ww, wr_t, ww_t, 0);
    // s3: heads b 128..255 after simA (independent of rt)
    cudaStreamWaitEvent(g_res.s3, g_res.eSA, 0);
    heads5_kernel<<<dim3(Nn/2048, 128), 256, 0, g_res.s3>>>(wr, ww, wr_t, ww_t, 128);
    cudaEventRecord(g_res.e3, g_res.s3);

    // tail: after simB, split remaining 256 batches across legacy + s2
    heads5_kernel<<<dim3(Nn/2048, 128), 256>>>(wr, ww, wr_t, ww_t, 256);        // legacy
    cudaStreamWaitEvent(g_res.s2, g_res.eSB, 0);
    heads5_kernel<<<dim3(Nn/2048, 128), 256, 0, g_res.s2>>>(wr, ww, wr_t, ww_t, 384);
    cudaEventRecord(g_res.e2, g_res.s2);

    cudaStreamWaitEvent(0, g_res.e1, 0);
    cudaStreamWaitEvent(0, g_res.e2, 0);
    cudaStreamWaitEvent(0, g_res.e3, 0);
}

// round 16
// speedup vs baseline: 1.3469x; 1.0093x over previous
#include <cuda_runtime.h>
#include <cuda_bf16.h>

#define Bb 512
#define Hh 1024
#define Nn 16384
#define Mm 128
#define Rr 4
#define Ss 3

#define PADK 40
#define PADW 136
#define PAD64 72

// ---------------- scratch ----------------
__device__ __align__(16) float g_k[Bb*Mm];
__device__ __align__(16) float g_e[Bb*Mm];
__device__ __align__(16) float g_a[Bb*Mm];
__device__ float g_beta[Bb], g_gate[Bb], g_slog[Bb*Ss], g_s[Bb*Ss];
__device__ float g_nk[Bb], g_nm[Nn], g_sum[Bb];   // INVERSE norms
__device__ __align__(16) __nv_bfloat16 g_t[(size_t)Bb*Nn];    // bf16
__device__ __align__(16) __nv_bfloat16 g_mbf[(size_t)Nn*Mm];  // bf16 copy of m

// ---------------- helpers ----------------
__device__ __forceinline__ void ldsm4(unsigned* r, const __nv_bfloat16* p) {
    unsigned a = (unsigned)__cvta_generic_to_shared(p);
    asm volatile("ldmatrix.sync.aligned.m8n8.x4.shared.b16 {%0,%1,%2,%3}, [%4];"
        : "=r"(r[0]), "=r"(r[1]), "=r"(r[2]), "=r"(r[3]) : "r"(a));
}
__device__ __forceinline__ void ldsm4t(unsigned* r, const __nv_bfloat16* p) {
    unsigned a = (unsigned)__cvta_generic_to_shared(p);
    asm volatile("ldmatrix.sync.aligned.m8n8.x4.trans.shared.b16 {%0,%1,%2,%3}, [%4];"
        : "=r"(r[0]), "=r"(r[1]), "=r"(r[2]), "=r"(r[3]) : "r"(a));
}
__device__ __forceinline__ void mma16816(float* c, const unsigned* a, const unsigned* b) {
    asm volatile("mma.sync.aligned.m16n8k16.row.col.f32.bf16.bf16.f32 "
        "{%0,%1,%2,%3}, {%4,%5,%6,%7}, {%8,%9}, {%0,%1,%2,%3};"
        : "+f"(c[0]), "+f"(c[1]), "+f"(c[2]), "+f"(c[3])
        : "r"(a[0]), "r"(a[1]), "r"(a[2]), "r"(a[3]), "r"(b[0]), "r"(b[1]));
}
__device__ __forceinline__ void cvt_store8(__nv_bfloat16* dst, float4 v0, float4 v1) {
    __nv_bfloat162* d = (__nv_bfloat162*)dst;
    d[0] = __float22bfloat162_rn(make_float2(v0.x, v0.y));
    d[1] = __float22bfloat162_rn(make_float2(v0.z, v0.w));
    d[2] = __float22bfloat162_rn(make_float2(v1.x, v1.y));
    d[3] = __float22bfloat162_rn(make_float2(v1.z, v1.w));
}
// exp2 on the FMA pipe — no MUFU.
__device__ __forceinline__ float fast_exp2(float x) {
    float t = x + 12582912.0f;
    int ri = __float_as_int(t) - 0x4B400000;
    float f = x - (t - 12582912.0f);
    float p = 0.0013333558f;
    p = fmaf(p, f, 0.0096181298f);
    p = fmaf(p, f, 0.0555041087f);
    p = fmaf(p, f, 0.2402265070f);
    p = fmaf(p, f, 0.6931471806f);
    p = fmaf(p, f, 1.0f);
    return __int_as_float(__float_as_int(p) + (ri << 23));
}

// ---------------- kernel 1: controller projections (8x j-parallel) ----------------
__global__ __launch_bounds__(256) void ctrl_kernel(
    const float* __restrict__ h,
    const float* __restrict__ kw, const float* __restrict__ kb,
    const float* __restrict__ bw, const float* __restrict__ bbv,
    const float* __restrict__ gw, const float* __restrict__ gb,
    const float* __restrict__ sw, const float* __restrict__ sb,
    const float* __restrict__ ew, const float* __restrict__ eb,
    const float* __restrict__ aw, const float* __restrict__ ab)
{
    __shared__ float h_s[8][Hh];
    int b0 = blockIdx.x * 8;
    for (int i = threadIdx.x; i < 8*Hh; i += 256)
        h_s[i >> 10][i & 1023] = h[(size_t)(b0 + (i >> 10))*Hh + (i & 1023)];
    __syncthreads();
    int warp = threadIdx.x >> 5, lane = threadIdx.x & 31;
    for (int j = blockIdx.y*8 + warp; j < 3*Mm + 5; j += 64) {
        const float* wrow; float bias; int act;
        if (j < Mm)        { wrow = kw + (size_t)j*Hh;        bias = kb[j];      act = 0; }
        else if (j < 2*Mm) { wrow = ew + (size_t)(j-Mm)*Hh;   bias = eb[j-Mm];   act = 0; }
        else if (j < 3*Mm) { wrow = aw + (size_t)(j-2*Mm)*Hh; bias = ab[j-2*Mm]; act = 0; }
        else if (j == 384) { wrow = bw;                       bias = bbv[0];     act = 2; }
        else if (j == 385) { wrow = gw;                       bias = gb[0];      act = 0; }
        else               { wrow = sw + (size_t)(j-386)*Hh;  bias = sb[j-386];  act = 3; }
        float acc[8];
        #pragma unroll
        for (int q = 0; q < 8; q++) acc[q] = 0.f;
        for (int k = lane; k < Hh; k += 32) {
            float wv = __ldg(wrow + k);
            #pragma unroll
            for (int q = 0; q < 8; q++) acc[q] = fmaf(wv, h_s[q][k], acc[q]);
        }
        #pragma unroll
        for (int q = 0; q < 8; q++) {
            float v = acc[q];
            #pragma unroll
            for (int o = 16; o; o >>= 1) v += __shfl_down_sync(0xffffffffu, v, o);
            if (lane == 0) {
                v += bias;
                if (act == 0) v = fminf(fmaxf(v, 0.f), 1.f);
                else if (act == 2) v = fmaxf(v, 0.f);
                int b = b0 + q;
                if (j < Mm)        g_k[b*Mm + j] = v;
                else if (j < 2*Mm) g_e[b*Mm + (j-Mm)] = v;
                else if (j < 3*Mm) g_a[b*Mm + (j-2*Mm)] = v;
                else if (j == 384) g_beta[b] = v;
                else if (j == 385) g_gate[b] = v;
                else               g_slog[b*Ss + (j-386)] = v;
            }
        }
    }
}

// ---------------- kernel 2a: m inverse norms + bf16 copy + zero r_t ----------------
__global__ __launch_bounds__(256) void prep_m_kernel(const float* __restrict__ m, float* __restrict__ r_out)
{
    int warp = threadIdx.x >> 5, lane = threadIdx.x & 31;
    int bidx = blockIdx.x;
    if (bidx < 2048) {
        int n = bidx*8 + warp;
        float4 v = *(const float4*)(m + (size_t)n*Mm + lane*4);
        __nv_bfloat162* dst = (__nv_bfloat162*)(g_mbf + (size_t)n*Mm + lane*4);
        dst[0] = __float22bfloat162_rn(make_float2(v.x, v.y));
        dst[1] = __float22bfloat162_rn(make_float2(v.z, v.w));
        float ss = v.x*v.x + v.y*v.y + v.z*v.z + v.w*v.w;
        #pragma unroll
        for (int o = 16; o; o >>= 1) ss += __shfl_down_sync(0xffffffffu, ss, o);
        if (lane == 0) g_nm[n] = (ss > 0.f) ? 1.f/sqrtf(ss) : 0.f;
    } else {
        int base = (bidx-2048)*2048 + threadIdx.x*8;
        float4 z = make_float4(0.f,0.f,0.f,0.f);
        *(float4*)(r_out + base)     = z;
        *(float4*)(r_out + base + 4) = z;
    }
}

// ---------------- kernel 2b: k inverse norms + shift softmax ----------------
__global__ __launch_bounds__(256) void prep_k_kernel()
{
    int warp = threadIdx.x >> 5, lane = threadIdx.x & 31;
    int b = blockIdx.x*8 + warp;
    float4 v = *(const float4*)(g_k + (size_t)b*Mm + lane*4);
    float ss = v.x*v.x + v.y*v.y + v.z*v.z + v.w*v.w;
    #pragma unroll
    for (int o = 16; o; o >>= 1) ss += __shfl_down_sync(0xffffffffu, ss, o);
    if (lane == 0) {
        g_nk[b] = (ss > 0.f) ? 1.f/sqrtf(ss) : 0.f;
        g_sum[b] = 0.f;
        float x0 = g_slog[b*Ss+0], x1 = g_slog[b*Ss+1], x2 = g_slog[b*Ss+2];
        float mx = fmaxf(x0, fmaxf(x1, x2));
        float e0 = expf(x0-mx), e1 = expf(x1-mx), e2 = expf(x2-mx);
        float it = 1.f / (e0+e1+e2);
        g_s[b*Ss+0] = e0*it; g_s[b*Ss+1] = e1*it; g_s[b*Ss+2] = e2*it;
    }
}

// ---------------- kernel 3: sim GEMM + poly-exp2 + row sums (bf16 g_t out) ----------------
__global__ __launch_bounds__(256) void sim_hmma(int b_off)
{
    __shared__ __align__(16) __nv_bfloat16 As[128*PADK];
    __shared__ __align__(16) __nv_bfloat16 Bs[128*PADK];
    __shared__ float ssum[128];
    int tid = threadIdx.x, lane = tid & 31, w = tid >> 5;
    int n0 = blockIdx.x * 128, b0 = blockIdx.y * 128 + b_off;
    int wm = (w >> 1) * 32, wn = (w & 1) * 64;
    float acc[2][8][4];
    #pragma unroll
    for (int i = 0; i < 2; i++)
        #pragma unroll
        for (int j = 0; j < 8; j++)
            #pragma unroll
            for (int q = 0; q < 4; q++) acc[i][j][q] = 0.f;
    if (tid < 128) ssum[tid] = 0.f;
    int rowt = tid >> 1, kbt = (tid & 1) * 16;
    const float* ap = g_k + (size_t)(b0 + rowt)*Mm + kbt;
    const __nv_bfloat16* bp = g_mbf + (size_t)(n0 + rowt)*Mm + kbt;
    float4 ra0 = *(const float4*)(ap),   ra1 = *(const float4*)(ap+4),
           ra2 = *(const float4*)(ap+8), ra3 = *(const float4*)(ap+12);
    uint4 rb0 = *(const uint4*)(bp), rb1 = *(const uint4*)(bp+8);
    #pragma unroll
    for (int it = 0; it < 4; it++) {
        cvt_store8(&As[rowt*PADK + kbt],     ra0, ra1);
        cvt_store8(&As[rowt*PADK + kbt + 8], ra2, ra3);
        *(uint4*)(&Bs[rowt*PADK + kbt])     = rb0;
        *(uint4*)(&Bs[rowt*PADK + kbt + 8]) = rb1;
        __syncthreads();
        if (it < 3) {
            ap += 32; bp += 32;
            ra0 = *(const float4*)(ap);   ra1 = *(const float4*)(ap+4);
            ra2 = *(const float4*)(ap+8); ra3 = *(const float4*)(ap+12);
            rb0 = *(const uint4*)(bp); rb1 = *(const uint4*)(bp+8);
        }
        #pragma unroll
        for (int kk = 0; kk < 32; kk += 16) {
            unsigned af[2][4], bf[4][4];
            #pragma unroll
            for (int i = 0; i < 2; i++)
                ldsm4(af[i], &As[(wm + i*16 + (lane & 15))*PADK + kk + (lane >> 4)*8]);
            #pragma unroll
            for (int j = 0; j < 4; j++)
                ldsm4(bf[j], &Bs[(wn + j*16 + (lane & 7) + ((lane >> 4) & 1)*8)*PADK
                                  + kk + ((lane >> 3) & 1)*8]);
            #pragma unroll
            for (int i = 0; i < 2; i++)
                #pragma unroll
                for (int j = 0; j < 4; j++) {
                    mma16816(acc[i][2*j],   af[i], &bf[j][0]);
                    mma16816(acc[i][2*j+1], af[i], &bf[j][2]);
                }
        }
        __syncthreads();
    }
    int r4 = lane >> 2, c2 = (lane & 3)*2;
    #pragma unroll
    for (int i = 0; i < 2; i++) {
        #pragma unroll
        for (int rs = 0; rs < 2; rs++) {
            int bl = wm + i*16 + rs*8 + r4;
            int bg = b0 + bl;
            float be2 = g_beta[bg] * 1.44269504f * g_nk[bg];
            float rsum = 0.f;
            #pragma unroll
            for (int j8 = 0; j8 < 8; j8++) {
                int ng0 = n0 + wn + j8*8 + c2;
                float v0 = fast_exp2(be2 * acc[i][j8][rs*2]   * g_nm[ng0]);
                float v1 = fast_exp2(be2 * acc[i][j8][rs*2+1] * g_nm[ng0+1]);
                *(__nv_bfloat162*)(g_t + (size_t)bg*Nn + ng0) =
                    __float22bfloat162_rn(make_float2(v0, v1));
                rsum += v0 + v1;
            }
            atomicAdd(&ssum[bl], rsum);
        }
    }
    __syncthreads();
    if (tid < 128) atomicAdd(&g_sum[b0 + tid], ssum[tid]);
}

// ---------------- kernel 4: head weight update, one (b, head) per block ----------------
// grid (Nn/2048, nb, 5). 3 memory streams per block: g_t, prev, out.
__global__ __launch_bounds__(256) void heads6_kernel(
    const float* __restrict__ wr, const float* __restrict__ ww,
    float* __restrict__ wr_t, float* __restrict__ ww_t, int b_off)
{
    int b = blockIdx.y + b_off;
    int hd = blockIdx.z;
    int n = blockIdx.x * 2048 + threadIdx.x * 8;
    int lane = threadIdx.x & 31;
    float inv = 1.f / g_sum[b];
    float g = g_gate[b], omg = 1.f - g;
    float s0 = g_s[b*Ss+0], s1 = g_s[b*Ss+1], s2 = g_s[b*Ss+2];
    const __nv_bfloat16* gt = g_t + (size_t)b * Nn;

    const float* prev; float* outp;
    if (hd == 0) { prev = ww + (size_t)b*Nn; outp = ww_t + (size_t)b*Nn; }
    else {
        size_t off = ((size_t)(hd-1)*Bb + b) * Nn;
        prev = wr + off; outp = wr_t + off;
    }
    uint4 wraw = *(const uint4*)(gt + n);
    float4 pa = *(const float4*)(prev + n);
    float4 pb = *(const float4*)(prev + n + 4);

    float wcv[10];
    {
        float2 q0 = __bfloat1622float2(*(__nv_bfloat162*)&wraw.x);
        float2 q1 = __bfloat1622float2(*(__nv_bfloat162*)&wraw.y);
        float2 q2 = __bfloat1622float2(*(__nv_bfloat162*)&wraw.z);
        float2 q3 = __bfloat1622float2(*(__nv_bfloat162*)&wraw.w);
        wcv[1]=q0.x*inv; wcv[2]=q0.y*inv; wcv[3]=q1.x*inv; wcv[4]=q1.y*inv;
        wcv[5]=q2.x*inv; wcv[6]=q2.y*inv; wcv[7]=q3.x*inv; wcv[8]=q3.y*inv;
    }
    wcv[0] = __shfl_up_sync(0xffffffffu, wcv[8], 1);
    wcv[9] = __shfl_down_sync(0xffffffffu, wcv[1], 1);
    float pl = __shfl_up_sync(0xffffffffu, pb.w, 1);
    float pr = __shfl_down_sync(0xffffffffu, pa.x, 1);
    if (lane == 0) {
        int nl = (n - 1 + Nn) & (Nn - 1);
        wcv[0] = __bfloat162float(gt[nl]) * inv;
        pl = __ldg(prev + nl);
    }
    if (lane == 31) {
        int nr = (n + 8) & (Nn - 1);
        wcv[9] = __bfloat162float(gt[nr]) * inv;
        pr = __ldg(prev + nr);
    }
    float pv[10];
    pv[0]=pl;
    pv[1]=pa.x; pv[2]=pa.y; pv[3]=pa.z; pv[4]=pa.w;
    pv[5]=pb.x; pv[6]=pb.y; pv[7]=pb.z; pv[8]=pb.w;
    pv[9]=pr;
    float wg[10];
    #pragma unroll
    for (int q = 0; q < 10; q++) wg[q] = fmaf(g, wcv[q], omg*pv[q]);
    float4 oa, ob;
    oa.x = s0*wg[2] + s1*wg[1] + s2*wg[0];
    oa.y = s0*wg[3] + s1*wg[2] + s2*wg[1];
    oa.z = s0*wg[4] + s1*wg[3] + s2*wg[2];
    oa.w = s0*wg[5] + s1*wg[4] + s2*wg[3];
    ob.x = s0*wg[6] + s1*wg[5] + s2*wg[4];
    ob.y = s0*wg[7] + s1*wg[6] + s2*wg[5];
    ob.z = s0*wg[8] + s1*wg[7] + s2*wg[6];
    ob.w = s0*wg[9] + s1*wg[8] + s2*wg[7];
    *(float4*)(outp + n)     = oa;
    *(float4*)(outp + n + 4) = ob;
}

// ---------------- kernel 5: fused erase+add GEMM + m_t epilogue ----------------
__global__ __launch_bounds__(256) void memfused_hmma(
    const float* __restrict__ ww, const float* __restrict__ m, float* __restrict__ m_t)
{
    __shared__ __align__(16) __nv_bfloat16 As[32*PAD64];
    __shared__ __align__(16) __nv_bfloat16 Be[32*PADW];
    __shared__ __align__(16) __nv_bfloat16 Ba[32*PADW];
    int tid = threadIdx.x, lane = tid & 31, w = tid >> 5;
    int n0 = blockIdx.x * 64;
    int wm = (w >> 2) * 32, wn = (w & 3) * 32;
    float ae[2][4][4], aa[2][4][4];
    #pragma unroll
    for (int i = 0; i < 2; i++)
        #pragma unroll
        for (int j = 0; j < 4; j++)
            #pragma unroll
            for (int q = 0; q < 4; q++) { ae[i][j][q] = 0.f; aa[i][j][q] = 0.f; }
    int arw = tid >> 3, acl = (tid & 7) * 8;
    int brw = tid >> 3, bcl = (tid & 7) * 16;
    for (int bc = 0; bc < Bb; bc += 32) {
        const float* apw = ww + (size_t)(bc + arw)*Nn + n0 + acl;
        float4 a0 = *(const float4*)(apw), a1 = *(const float4*)(apw+4);
        cvt_store8(&As[arw*PAD64 + acl], a0, a1);
        const float* ep = g_e + (size_t)(bc + brw)*Mm + bcl;
        float4 e0 = *(const float4*)(ep),   e1 = *(const float4*)(ep+4),
               e2 = *(const float4*)(ep+8), e3 = *(const float4*)(ep+12);
        cvt_store8(&Be[brw*PADW + bcl],     e0, e1);
        cvt_store8(&Be[brw*PADW + bcl + 8], e2, e3);
        const float* apb = g_a + (size_t)(bc + brw)*Mm + bcl;
        float4 f0 = *(const float4*)(apb),   f1 = *(const float4*)(apb+4),
               f2 = *(const float4*)(apb+8), f3 = *(const float4*)(apb+12);
        cvt_store8(&Ba[brw*PADW + bcl],     f0, f1);
        cvt_store8(&Ba[brw*PADW + bcl + 8], f2, f3);
        __syncthreads();
        #pragma unroll
        for (int kk = 0; kk < 32; kk += 16) {
            unsigned af[2][4], bfe[2][4], bfa[2][4];
            #pragma unroll
            for (int i = 0; i < 2; i++)
                ldsm4t(af[i], &As[(kk + (lane & 7) + ((lane >> 4) & 1)*8)*PAD64
                                   + wm + i*16 + ((lane >> 3) & 1)*8]);
            #pragma unroll
            for (int j = 0; j < 2; j++) {
                ldsm4t(bfe[j], &Be[(kk + (lane & 15))*PADW + wn + j*16 + (lane >> 4)*8]);
                ldsm4t(bfa[j], &Ba[(kk + (lane & 15))*PADW + wn + j*16 + (lane >> 4)*8]);
            }
            #pragma unroll
            for (int i = 0; i < 2; i++)
                #pragma unroll
                for (int j = 0; j < 2; j++) {
                    mma16816(ae[i][2*j],   af[i], &bfe[j][0]);
                    mma16816(ae[i][2*j+1], af[i], &bfe[j][2]);
                    mma16816(aa[i][2*j],   af[i], &bfa[j][0]);
                    mma16816(aa[i][2*j+1], af[i], &bfa[j][2]);
                }
        }
        __syncthreads();
    }
    int r4 = lane >> 2, c2 = (lane & 3)*2;
    #pragma unroll
    for (int i = 0; i < 2; i++) {
        #pragma unroll
        for (int j8 = 0; j8 < 4; j8++) {
            int col = wn + j8*8 + c2;
            #pragma unroll
            for (int rs = 0; rs < 2; rs++) {
                int row = n0 + wm + i*16 + rs*8 + r4;
                float me0 = ae[i][j8][rs*2], me1 = ae[i][j8][rs*2+1];
                float ma0 = aa[i][j8][rs*2], ma1 = aa[i][j8][rs*2+1];
                float2 mv = *(const float2*)(m + (size_t)row*Mm + col);
                float2 o;
                o.x = mv.x * (1.f - me0) + ma0;
                o.y = mv.y * (1.f - me1) + ma1;
                *(float2*)(m_t + (size_t)row*Mm + col) = o;
            }
        }
    }
}

// ---------------- kernel 6: r_t GEMM (bf16, split-K=16, red.v2) ----------------
__global__ __launch_bounds__(256, 2) void rt_hmma4(
    const float* __restrict__ wr, float* __restrict__ r_out)
{
    __shared__ __align__(16) __nv_bfloat16 As[2][64*PADK];
    __shared__ __align__(16) __nv_bfloat16 Bs[2][32*PADW];
    int tid = threadIdx.x, lane = tid & 31, w = tid >> 5;
    int row0 = blockIdx.x * 64;
    int kb = blockIdx.y * 1024;
    int wm = (w >> 2) * 32, wn = (w & 3) * 32;
    float acc[2][4][4];
    #pragma unroll
    for (int i = 0; i < 2; i++)
        #pragma unroll
        for (int j = 0; j < 4; j++)
            #pragma unroll
            for (int q = 0; q < 4; q++) acc[i][j][q] = 0.f;
    int arow = tid >> 2, akb = (tid & 3) * 8;
    int brow = tid >> 3, bnb = (tid & 7) * 16;
    const float* aptr = wr + (size_t)(row0 + arow)*Nn + kb + akb;
    const __nv_bfloat16* bptr = g_mbf + (size_t)(kb + brow)*Mm + bnb;
    float4 ra0 = *(const float4*)(aptr), ra1 = *(const float4*)(aptr+4);
    uint4 rb0 = *(const uint4*)(bptr), rb1 = *(const uint4*)(bptr+8);
    for (int it = 0; it < 32; it++) {
        __nv_bfloat16* Ab = As[it & 1];
        __nv_bfloat16* Bbf = Bs[it & 1];
        cvt_store8(&Ab[arow*PADK + akb], ra0, ra1);
        *(uint4*)(&Bbf[brow*PADW + bnb])     = rb0;
        *(uint4*)(&Bbf[brow*PADW + bnb + 8]) = rb1;
        if (it < 31) {
            aptr += 32; bptr += (size_t)32 * Mm;
            ra0 = *(const float4*)(aptr); ra1 = *(const float4*)(aptr+4);
            rb0 = *(const uint4*)(bptr); rb1 = *(const uint4*)(bptr+8);
        }
        __syncthreads();
        #pragma unroll
        for (int kk = 0; kk < 32; kk += 16) {
            unsigned af[2][4], bf[2][4];
            #pragma unroll
            for (int i = 0; i < 2; i++)
                ldsm4(af[i], &Ab[(wm + i*16 + (lane & 15))*PADK + kk + (lane >> 4)*8]);
            #pragma unroll
            for (int j = 0; j < 2; j++)
                ldsm4t(bf[j], &Bbf[(kk + (lane & 15))*PADW + wn + j*16 + (lane >> 4)*8]);
            #pragma unroll
            for (int i = 0; i < 2; i++)
                #pragma unroll
                for (int j = 0; j < 2; j++) {
                    mma16816(acc[i][2*j],   af[i], &bf[j][0]);
                    mma16816(acc[i][2*j+1], af[i], &bf[j][2]);
                }
        }
    }
    int r4 = lane >> 2, c2 = (lane & 3)*2;
    #pragma unroll
    for (int i = 0; i < 2; i++) {
        #pragma unroll
        for (int rs = 0; rs < 2; rs++) {
            int rb = row0 + wm + i*16 + rs*8 + r4;
            int r = rb >> 9, b = rb & (Bb - 1);
            float* dst = r_out + ((size_t)b*Rr + r)*Mm;
            #pragma unroll
            for (int j8 = 0; j8 < 4; j8++) {
                int col = wn + j8*8 + c2;
                asm volatile("red.global.add.v2.f32 [%0], {%1, %2};"
                    :: "l"(dst + col), "f"(acc[i][j8][rs*2]), "f"(acc[i][j8][rs*2+1])
                    : "memory");
            }
        }
    }
}

// ---------------- streams/events ----------------
namespace {
struct HostRes {
    cudaStream_t s1, s2, s3;
    cudaEvent_t e0, eC, eM, eSA, eSB, e1, e2, e3;
    HostRes() {
        cudaStreamCreateWithFlags(&s1, cudaStreamNonBlocking);
        cudaStreamCreateWithFlags(&s2, cudaStreamNonBlocking);
        cudaStreamCreateWithFlags(&s3, cudaStreamNonBlocking);
        cudaEventCreateWithFlags(&e0, cudaEventDisableTiming);
        cudaEventCreateWithFlags(&eC, cudaEventDisableTiming);
        cudaEventCreateWithFlags(&eM, cudaEventDisableTiming);
        cudaEventCreateWithFlags(&eSA, cudaEventDisableTiming);
        cudaEventCreateWithFlags(&eSB, cudaEventDisableTiming);
        cudaEventCreateWithFlags(&e1, cudaEventDisableTiming);
        cudaEventCreateWithFlags(&e2, cudaEventDisableTiming);
        cudaEventCreateWithFlags(&e3, cudaEventDisableTiming);
    }
};
HostRes g_res;
}

// ---------------- launch ----------------
extern "C" void kernel_launch(void* const* d_in, const int* in_sizes, int n_in,
                              void* d_out, int out_size)
{
    const float* h_t = (const float*)d_in[0];
    const float* wr  = (const float*)d_in[1];
    const float* ww  = (const float*)d_in[2];
    const float* m   = (const float*)d_in[3];
    const float* kw  = (const float*)d_in[4];
    const float* kb  = (const float*)d_in[5];
    const float* bw  = (const float*)d_in[6];
    const float* bbv = (const float*)d_in[7];
    const float* gw  = (const float*)d_in[8];
    const float* gb  = (const float*)d_in[9];
    const float* sw  = (const float*)d_in[10];
    const float* sb  = (const float*)d_in[11];
    const float* ew  = (const float*)d_in[14];
    const float* eb  = (const float*)d_in[15];
    const float* aw  = (const float*)d_in[16];
    const float* ab  = (const float*)d_in[17];

    float* out  = (float*)d_out;
    float* r_t  = out;
    float* wr_t = out + (size_t)Bb*Rr*Mm;
    float* ww_t = wr_t + (size_t)Rr*Bb*Nn;
    float* m_t  = ww_t + (size_t)Bb*Nn;

    cudaEventRecord(g_res.e0, 0);   // root — pulls side streams into capture

    // s1: prep_m -> rt GEMM (bf16)
    cudaStreamWaitEvent(g_res.s1, g_res.e0, 0);
    prep_m_kernel<<<2176, 256, 0, g_res.s1>>>(m, r_t);
    cudaEventRecord(g_res.eM, g_res.s1);
    rt_hmma4<<<dim3(2048/64, 16), 256, 0, g_res.s1>>>(wr, r_t);
    cudaEventRecord(g_res.e1, g_res.s1);

    // legacy: ctrl -> prep_k
    ctrl_kernel<<<dim3(Bb/8, 8), 256>>>(h_t, kw, kb, bw, bbv, gw, gb, sw, sb, ew, eb, aw, ab);
    cudaEventRecord(g_res.eC, 0);
    prep_k_kernel<<<Bb/8, 256>>>();

    // s2: memfused after ctrl
    cudaStreamWaitEvent(g_res.s2, g_res.eC, 0);
    memfused_hmma<<<Nn/64, 256, 0, g_res.s2>>>(ww, m, m_t);

    // legacy: sim halves (chip-filling grids), needs prep_k + prep_m
    cudaStreamWaitEvent(0, g_res.eM, 0);
    sim_hmma<<<dim3(Nn/128, 2), 256>>>(0);          // b 0..255
    cudaEventRecord(g_res.eSA, 0);
    sim_hmma<<<dim3(Nn/128, 2), 256>>>(256);        // b 256..511
    cudaEventRecord(g_res.eSB, 0);

    // s2: heads b 0..127 (all 5 heads) after simA
    cudaStreamWaitEvent(g_res.s2, g_res.eSA, 0);
    heads6_kernel<<<dim3(Nn/2048, 128, 5), 256, 0, g_res.s2>>>(wr, ww, wr_t, ww_t, 0);
    // s3: heads b 128..255 after simA
    cudaStreamWaitEvent(g_res.s3, g_res.eSA, 0);
    heads6_kernel<<<dim3(Nn/2048, 128, 5), 256, 0, g_res.s3>>>(wr, ww, wr_t, ww_t, 128);
    cudaEventRecord(g_res.e3, g_res.s3);

    // tail: after simB, split remaining 256 batches across legacy + s2
    heads6_kernel<<<dim3(Nn/2048, 128, 5), 256>>>(wr, ww, wr_t, ww_t, 256);     // legacy
    cudaStreamWaitEvent(g_res.s2, g_res.eSB, 0);
    heads6_kernel<<<dim3(Nn/2048, 128, 5), 256, 0, g_res.s2>>>(wr, ww, wr_t, ww_t, 384);
    cudaEventRecord(g_res.e2, g_res.s2);

    cudaStreamWaitEvent(0, g_res.e1, 0);
    cudaStreamWaitEvent(0, g_res.e2, 0);
    cudaStreamWaitEvent(0, g_res.e3, 0);
}